// round 1
// baseline (speedup 1.0000x reference)
#include <cuda_runtime.h>

// LuongAttention: B=16, TQ=2048, TK=2048, D=1024
//  out = [context (B*TQ*D floats) | alignment (B*TQ*TK floats)]

static constexpr int Bsz = 16;
static constexpr int TQ  = 2048;
static constexpr int TK  = 2048;
static constexpr int D   = 1024;

// keys scratch: 16*2048*1024 floats = 134 MB (device global -> allocation-free)
__device__ float g_keys[(size_t)Bsz * TK * D];

#define BM 128
#define BN 128
#define BK 8
#define TM 8
#define TN 8
// 256 threads, 16x16 thread grid, each computes TM x TN = 8x8

// ---------------------------------------------------------------------------
// C[M,N] = A[M,K] * B[K,N] (+ bias[N] if bias != nullptr)
// batched via blockIdx.z with element strides sA/sB/sC
// ---------------------------------------------------------------------------
__global__ __launch_bounds__(256)
void sgemm_nn(const float* __restrict__ A, const float* __restrict__ B,
              const float* __restrict__ bias, float* __restrict__ C,
              int M, int N, int K,
              long long sA, long long sB, long long sC)
{
    A += (long long)blockIdx.z * sA;
    B += (long long)blockIdx.z * sB;
    C += (long long)blockIdx.z * sC;

    __shared__ float As[BK][BM];
    __shared__ float Bs[BK][BN];

    const int tid = threadIdx.x;
    const int tr  = tid >> 4;        // 0..15
    const int tc  = tid & 15;        // 0..15

    // A tile loader: 128 rows x 8 cols, 2 threads/row, float4 each
    const int rowA = tid >> 1;
    const int colA = (tid & 1) << 2;
    // B tile loader: 8 rows x 128 cols, 32 threads/row, float4 each
    const int rowB = tid >> 5;
    const int colB = (tid & 31) << 2;

    const float* Aptr = A + ((long long)(blockIdx.y * BM + rowA)) * K + colA;
    const float* Bptr = B + (long long)rowB * N + blockIdx.x * BN + colB;

    float acc[TM][TN] = {};
    float ra[TM], rb[TN];

    for (int k0 = 0; k0 < K; k0 += BK) {
        float4 a4 = *reinterpret_cast<const float4*>(Aptr);
        As[colA + 0][rowA] = a4.x;
        As[colA + 1][rowA] = a4.y;
        As[colA + 2][rowA] = a4.z;
        As[colA + 3][rowA] = a4.w;
        *reinterpret_cast<float4*>(&Bs[rowB][colB]) =
            *reinterpret_cast<const float4*>(Bptr);
        __syncthreads();

        Aptr += BK;
        Bptr += (long long)BK * N;

#pragma unroll
        for (int k = 0; k < BK; ++k) {
#pragma unroll
            for (int i = 0; i < TM; ++i) ra[i] = As[k][tr * TM + i];
#pragma unroll
            for (int j = 0; j < TN; ++j) rb[j] = Bs[k][tc * TN + j];
#pragma unroll
            for (int i = 0; i < TM; ++i)
#pragma unroll
                for (int j = 0; j < TN; ++j)
                    acc[i][j] += ra[i] * rb[j];
        }
        __syncthreads();
    }

    const int colBase = blockIdx.x * BN + tc * TN;
    float badd[TN];
#pragma unroll
    for (int j = 0; j < TN; ++j)
        badd[j] = bias ? bias[colBase + j] : 0.0f;

#pragma unroll
    for (int i = 0; i < TM; ++i) {
        const int row = blockIdx.y * BM + tr * TM + i;
        float* Cp = C + (long long)row * N + colBase;
        float4 v0, v1;
        v0.x = acc[i][0] + badd[0]; v0.y = acc[i][1] + badd[1];
        v0.z = acc[i][2] + badd[2]; v0.w = acc[i][3] + badd[3];
        v1.x = acc[i][4] + badd[4]; v1.y = acc[i][5] + badd[5];
        v1.z = acc[i][6] + badd[6]; v1.w = acc[i][7] + badd[7];
        reinterpret_cast<float4*>(Cp)[0] = v0;
        reinterpret_cast<float4*>(Cp)[1] = v1;
    }
}

// ---------------------------------------------------------------------------
// C[M,N] = A[M,K] * B[N,K]^T   (both row-major with K contiguous)
// batched via blockIdx.z
// ---------------------------------------------------------------------------
__global__ __launch_bounds__(256)
void sgemm_nt(const float* __restrict__ A, const float* __restrict__ B,
              float* __restrict__ C,
              int M, int N, int K,
              long long sA, long long sB, long long sC)
{
    A += (long long)blockIdx.z * sA;
    B += (long long)blockIdx.z * sB;
    C += (long long)blockIdx.z * sC;

    __shared__ float As[BK][BM];
    __shared__ float Bs[BK][BN];

    const int tid = threadIdx.x;
    const int tr  = tid >> 4;
    const int tc  = tid & 15;

    const int rowA = tid >> 1;
    const int colA = (tid & 1) << 2;

    const float* Aptr = A + ((long long)(blockIdx.y * BM + rowA)) * K + colA;
    // B rows (n-index) x k, same access shape as A
    const float* Bptr = B + ((long long)(blockIdx.x * BN + rowA)) * K + colA;

    float acc[TM][TN] = {};
    float ra[TM], rb[TN];

    for (int k0 = 0; k0 < K; k0 += BK) {
        float4 a4 = *reinterpret_cast<const float4*>(Aptr);
        As[colA + 0][rowA] = a4.x;
        As[colA + 1][rowA] = a4.y;
        As[colA + 2][rowA] = a4.z;
        As[colA + 3][rowA] = a4.w;
        float4 b4 = *reinterpret_cast<const float4*>(Bptr);
        Bs[colA + 0][rowA] = b4.x;
        Bs[colA + 1][rowA] = b4.y;
        Bs[colA + 2][rowA] = b4.z;
        Bs[colA + 3][rowA] = b4.w;
        __syncthreads();

        Aptr += BK;
        Bptr += BK;

#pragma unroll
        for (int k = 0; k < BK; ++k) {
#pragma unroll
            for (int i = 0; i < TM; ++i) ra[i] = As[k][tr * TM + i];
#pragma unroll
            for (int j = 0; j < TN; ++j) rb[j] = Bs[k][tc * TN + j];
#pragma unroll
            for (int i = 0; i < TM; ++i)
#pragma unroll
                for (int j = 0; j < TN; ++j)
                    acc[i][j] += ra[i] * rb[j];
        }
        __syncthreads();
    }

#pragma unroll
    for (int i = 0; i < TM; ++i) {
        const int row = blockIdx.y * BM + tr * TM + i;
        float* Cp = C + (long long)row * N + blockIdx.x * BN + tc * TN;
        float4 v0, v1;
        v0.x = acc[i][0]; v0.y = acc[i][1]; v0.z = acc[i][2]; v0.w = acc[i][3];
        v1.x = acc[i][4]; v1.y = acc[i][5]; v1.z = acc[i][6]; v1.w = acc[i][7];
        reinterpret_cast<float4*>(Cp)[0] = v0;
        reinterpret_cast<float4*>(Cp)[1] = v1;
    }
}

// ---------------------------------------------------------------------------
// In-place row softmax over 2048 columns; one block (256 threads) per row.
// ---------------------------------------------------------------------------
__global__ __launch_bounds__(256)
void softmax2048(float* __restrict__ data)
{
    float* row = data + (long long)blockIdx.x * 2048;
    const int tid = threadIdx.x;

    float4 v0 = reinterpret_cast<float4*>(row)[tid];
    float4 v1 = reinterpret_cast<float4*>(row)[tid + 256];

    __shared__ float sm[8];
    __shared__ float bcast;

    // --- max ---
    float m = fmaxf(fmaxf(fmaxf(v0.x, v0.y), fmaxf(v0.z, v0.w)),
                    fmaxf(fmaxf(v1.x, v1.y), fmaxf(v1.z, v1.w)));
#pragma unroll
    for (int o = 16; o > 0; o >>= 1)
        m = fmaxf(m, __shfl_xor_sync(0xffffffffu, m, o));
    if ((tid & 31) == 0) sm[tid >> 5] = m;
    __syncthreads();
    if (tid == 0) {
        float t = sm[0];
#pragma unroll
        for (int i = 1; i < 8; ++i) t = fmaxf(t, sm[i]);
        bcast = t;
    }
    __syncthreads();
    m = bcast;
    __syncthreads();   // protect sm before reuse

    // --- exp + sum ---
    v0.x = __expf(v0.x - m); v0.y = __expf(v0.y - m);
    v0.z = __expf(v0.z - m); v0.w = __expf(v0.w - m);
    v1.x = __expf(v1.x - m); v1.y = __expf(v1.y - m);
    v1.z = __expf(v1.z - m); v1.w = __expf(v1.w - m);
    float s = (v0.x + v0.y) + (v0.z + v0.w) + (v1.x + v1.y) + (v1.z + v1.w);
#pragma unroll
    for (int o = 16; o > 0; o >>= 1)
        s += __shfl_xor_sync(0xffffffffu, s, o);
    if ((tid & 31) == 0) sm[tid >> 5] = s;
    __syncthreads();
    if (tid == 0) {
        float t = 0.0f;
#pragma unroll
        for (int i = 0; i < 8; ++i) t += sm[i];
        bcast = 1.0f / t;
    }
    __syncthreads();
    const float r = bcast;

    v0.x *= r; v0.y *= r; v0.z *= r; v0.w *= r;
    v1.x *= r; v1.y *= r; v1.z *= r; v1.w *= r;
    reinterpret_cast<float4*>(row)[tid]       = v0;
    reinterpret_cast<float4*>(row)[tid + 256] = v1;
}

// ---------------------------------------------------------------------------
extern "C" void kernel_launch(void* const* d_in, const int* in_sizes, int n_in,
                              void* d_out, int out_size)
{
    const float* dec = (const float*)d_in[0];   // [B, TQ, D]
    const float* enc = (const float*)d_in[1];   // [B, TK, D]
    const float* Wk  = (const float*)d_in[2];   // [D, D]
    const float* bia = (const float*)d_in[3];   // [D]
    // defensive: if kernel/bias order ever differs, distinguish by size
    if (n_in >= 4 && in_sizes[2] == D && in_sizes[3] == D * D) {
        const float* t = Wk; Wk = bia; bia = t;
    }

    float* out     = (float*)d_out;
    float* context = out;                                   // B*TQ*D
    float* align   = out + (size_t)Bsz * TQ * D;            // B*TQ*TK (also score scratch)

    float* keys = nullptr;
    cudaGetSymbolAddress((void**)&keys, g_keys);

    const dim3 blk(256);

    // K1: keys[B*TK, D] = enc[B*TK, D] @ W[D, D] + bias
    sgemm_nn<<<dim3(D / BN, (Bsz * TK) / BM, 1), blk>>>(
        enc, Wk, bia, keys, Bsz * TK, D, D, 0LL, 0LL, 0LL);

    // K2: score[b] = dec[b] @ keys[b]^T  -> written into alignment region
    sgemm_nt<<<dim3(TK / BN, TQ / BM, Bsz), blk>>>(
        dec, keys, align, TQ, TK, D,
        (long long)TQ * D, (long long)TK * D, (long long)TQ * TK);

    // K3: in-place softmax over TK
    softmax2048<<<Bsz * TQ, 256>>>(align);

    // K4: context[b] = align[b] @ enc[b]
    sgemm_nn<<<dim3(D / BN, TQ / BM, Bsz), blk>>>(
        align, enc, nullptr, context, TQ, D, TK,
        (long long)TQ * TK, (long long)TK * D, (long long)TQ * D);
}

// round 3
// speedup vs baseline: 2.7697x; 2.7697x over previous
#include <cuda_runtime.h>
#include <cuda_bf16.h>
#include <cstdint>

// LuongAttention B=16, TQ=2048, TK=2048, D=1024
// out = [context (B*TQ*D fp32) | alignment (B*TQ*TK fp32)]
static constexpr int Bsz = 16;
static constexpr int TQ  = 2048;
static constexpr int TK  = 2048;
static constexpr int D   = 1024;

// ---------------- device scratch (allocation-free, 16B aligned for cp.async) --
__device__ __align__(16) __nv_bfloat16 g_dec_h[(size_t)Bsz * TQ * D];
__device__ __align__(16) __nv_bfloat16 g_dec_l[(size_t)Bsz * TQ * D];
__device__ __align__(16) __nv_bfloat16 g_enc_h[(size_t)Bsz * TK * D];
__device__ __align__(16) __nv_bfloat16 g_enc_l[(size_t)Bsz * TK * D];
__device__ __align__(16) __nv_bfloat16 g_encT_h[(size_t)Bsz * D * TK];
__device__ __align__(16) __nv_bfloat16 g_encT_l[(size_t)Bsz * D * TK];
__device__ __align__(16) __nv_bfloat16 g_Wt_h[(size_t)D * D];
__device__ __align__(16) __nv_bfloat16 g_Wt_l[(size_t)D * D];
__device__ __align__(16) __nv_bfloat16 g_key_h[(size_t)Bsz * TK * D];
__device__ __align__(16) __nv_bfloat16 g_key_l[(size_t)Bsz * TK * D];
__device__ __align__(16) __nv_bfloat16 g_al_h[(size_t)Bsz * TQ * TK];
__device__ __align__(16) __nv_bfloat16 g_al_l[(size_t)Bsz * TQ * TK];

// ---------------- helpers ----------------
__device__ __forceinline__ uint32_t smem_u32(const void* p) {
    uint32_t a;
    asm("{ .reg .u64 t; cvta.to.shared.u64 t, %1; cvt.u32.u64 %0, t; }"
        : "=r"(a) : "l"(p));
    return a;
}
__device__ __forceinline__ void cp_async16(uint32_t dst, const void* src) {
    asm volatile("{ .reg .u64 g; cvta.to.global.u64 g, %1;"
                 "  cp.async.cg.shared.global [%0], [g], 16; }"
                 :: "r"(dst), "l"(src) : "memory");
}
#define CP_COMMIT() asm volatile("cp.async.commit_group;" ::: "memory")
#define CP_WAIT1()  asm volatile("cp.async.wait_group 1;" ::: "memory")
#define CP_WAIT0()  asm volatile("cp.async.wait_group 0;" ::: "memory")

__device__ __forceinline__ void ldm_x4(uint32_t* r, uint32_t addr) {
    asm volatile("ldmatrix.sync.aligned.m8n8.x4.shared.b16 {%0,%1,%2,%3}, [%4];"
                 : "=r"(r[0]), "=r"(r[1]), "=r"(r[2]), "=r"(r[3]) : "r"(addr));
}
__device__ __forceinline__ void mma_bf16(float* c, const uint32_t* a, const uint32_t* b) {
    asm volatile("mma.sync.aligned.m16n8k16.row.col.f32.bf16.bf16.f32 "
                 "{%0,%1,%2,%3}, {%4,%5,%6,%7}, {%8,%9}, {%0,%1,%2,%3};"
                 : "+f"(c[0]), "+f"(c[1]), "+f"(c[2]), "+f"(c[3])
                 : "r"(a[0]), "r"(a[1]), "r"(a[2]), "r"(a[3]), "r"(b[0]), "r"(b[1]));
}
__device__ __forceinline__ void split2(float x, __nv_bfloat16& h, __nv_bfloat16& l) {
    h = __float2bfloat16_rn(x);
    l = __float2bfloat16_rn(x - __bfloat162float(h));
}

// smem geometry: padded stride 40 bf16 (80B) -> conflict-free ldmatrix
static constexpr int LDT = 40;
static constexpr int TILE_B  = 128 * LDT * 2;   // 10240 B per tile array
static constexpr int STAGE_B = 4 * TILE_B;      // Ah,Al,Bh,Bl
static constexpr int SMEM_DYN = 2 * STAGE_B;    // 81920 B double-buffered

// ---------------------------------------------------------------------------
// bf16x3 GEMM (emulated fp32) on mma.sync:  C[M,N] = A[M,K] * B[N,K]^T
// Tile 128x128, BK=32, 256 thr (8 warps, 2Mx4N, warp tile 64x32)
// grid = (N/128, M/128, batch)
// ---------------------------------------------------------------------------
__global__ __launch_bounds__(256, 2)
void gemm_bf16x3(const __nv_bfloat16* __restrict__ Ah, const __nv_bfloat16* __restrict__ Al,
                 const __nv_bfloat16* __restrict__ Bh, const __nv_bfloat16* __restrict__ Bl,
                 float* __restrict__ Cf,
                 __nv_bfloat16* __restrict__ Chi, __nv_bfloat16* __restrict__ Clo,
                 const float* __restrict__ bias,
                 int K, int ldC,
                 long long sA, long long sB, long long sC)
{
    extern __shared__ __align__(128) char sm[];
    const uint32_t s0 = smem_u32(sm);

    const int tid  = threadIdx.x;
    const int wid  = tid >> 5;
    const int lane = tid & 31;
    const int wm   = wid & 1;     // 0..1  (M)
    const int wn   = wid >> 1;    // 0..3  (N)

    const long long zA = (long long)blockIdx.z * sA;
    const long long zB = (long long)blockIdx.z * sB;
    const __nv_bfloat16* pAh = Ah + zA + (long long)(blockIdx.y * 128) * K;
    const __nv_bfloat16* pAl = Al + zA + (long long)(blockIdx.y * 128) * K;
    const __nv_bfloat16* pBh = Bh + zB + (long long)(blockIdx.x * 128) * K;
    const __nv_bfloat16* pBl = Bl + zB + (long long)(blockIdx.x * 128) * K;

    // loader: 512 16B-chunks per array, 2 per thread
    const int lr0 = tid >> 2;           // row 0..63
    const int lc  = tid & 3;            // 16B chunk in row
    auto tileLoad = [&](int stage, int k0) {
        const uint32_t db = s0 + stage * STAGE_B;
#pragma unroll
        for (int i = 0; i < 2; ++i) {
            const int r = lr0 + i * 64;
            const uint32_t so = (uint32_t)(r * (LDT * 2) + lc * 16);
            const long long go = (long long)r * K + k0 + lc * 8;
            cp_async16(db + 0 * TILE_B + so, pAh + go);
            cp_async16(db + 1 * TILE_B + so, pAl + go);
            cp_async16(db + 2 * TILE_B + so, pBh + go);
            cp_async16(db + 3 * TILE_B + so, pBl + go);
        }
    };

    // lane-dependent ldmatrix base offsets (bytes)
    const uint32_t aOff = (uint32_t)(((wm * 64 + (lane & 15)) * LDT + ((lane >> 4) * 8)) * 2);
    const int bn = wn * 32 + (lane & 7) + ((lane & 16) >> 1);
    const uint32_t bOff = (uint32_t)((bn * LDT + (lane & 8)) * 2);

    float acc[4][4][4];
#pragma unroll
    for (int a = 0; a < 4; ++a)
#pragma unroll
        for (int b = 0; b < 4; ++b)
#pragma unroll
            for (int c = 0; c < 4; ++c) acc[a][b][c] = 0.0f;

    const int nk = K >> 5;
    tileLoad(0, 0);
    CP_COMMIT();

    for (int it = 0; it < nk; ++it) {
        if (it + 1 < nk) {
            tileLoad((it + 1) & 1, (it + 1) << 5);
            CP_COMMIT();
            CP_WAIT1();
        } else {
            CP_WAIT0();
        }
        __syncthreads();

        const uint32_t sb = s0 + (it & 1) * STAGE_B;
#pragma unroll
        for (int ks = 0; ks < 2; ++ks) {
            const uint32_t kso = ks * 32;            // 16 elements
            uint32_t fAh[4][4], fAl[4][4];
#pragma unroll
            for (int mt = 0; mt < 4; ++mt) {
                ldm_x4(fAh[mt], sb + 0 * TILE_B + aOff + kso + mt * 1280);
                ldm_x4(fAl[mt], sb + 1 * TILE_B + aOff + kso + mt * 1280);
            }
#pragma unroll
            for (int pp = 0; pp < 2; ++pp) {
                uint32_t fBh[4], fBl[4];
                ldm_x4(fBh, sb + 2 * TILE_B + bOff + kso + pp * 1280);
                ldm_x4(fBl, sb + 3 * TILE_B + bOff + kso + pp * 1280);
#pragma unroll
                for (int q = 0; q < 2; ++q) {
                    const int nt = pp * 2 + q;
#pragma unroll
                    for (int mt = 0; mt < 4; ++mt) {
                        mma_bf16(acc[mt][nt], fAh[mt], fBh + q * 2);
                        mma_bf16(acc[mt][nt], fAh[mt], fBl + q * 2);
                        mma_bf16(acc[mt][nt], fAl[mt], fBh + q * 2);
                    }
                }
            }
        }
        __syncthreads();
    }

    // ---------------- epilogue ----------------
    const int rBase = blockIdx.y * 128 + wm * 64 + (lane >> 2);
    const int cBase = blockIdx.x * 128 + wn * 32 + (lane & 3) * 2;
    const long long zC = (long long)blockIdx.z * sC;

#pragma unroll
    for (int mt = 0; mt < 4; ++mt) {
#pragma unroll
        for (int h = 0; h < 2; ++h) {
            const int row = rBase + mt * 16 + h * 8;
#pragma unroll
            for (int nt = 0; nt < 4; ++nt) {
                const int col = cBase + nt * 8;
                float v0 = acc[mt][nt][h * 2 + 0];
                float v1 = acc[mt][nt][h * 2 + 1];
                if (bias) { v0 += bias[col]; v1 += bias[col + 1]; }
                const long long o = zC + (long long)row * ldC + col;
                if (Cf) {
                    float2 fv; fv.x = v0; fv.y = v1;
                    *(float2*)(Cf + o) = fv;
                }
                if (Chi) {
                    __nv_bfloat16 h0, l0, h1, l1;
                    split2(v0, h0, l0); split2(v1, h1, l1);
                    __nv_bfloat162 hv; hv.x = h0; hv.y = h1;
                    __nv_bfloat162 lv; lv.x = l0; lv.y = l1;
                    *(__nv_bfloat162*)(Chi + o) = hv;
                    *(__nv_bfloat162*)(Clo + o) = lv;
                }
            }
        }
    }
}

// ---------------------------------------------------------------------------
// Elementwise fp32 -> (hi, lo) bf16 split
// ---------------------------------------------------------------------------
__global__ __launch_bounds__(256)
void convert_split(const float4* __restrict__ in, __nv_bfloat16* __restrict__ oh,
                   __nv_bfloat16* __restrict__ ol, int n4)
{
    __nv_bfloat162* oh2 = reinterpret_cast<__nv_bfloat162*>(oh);
    __nv_bfloat162* ol2 = reinterpret_cast<__nv_bfloat162*>(ol);
    for (int i = blockIdx.x * 256 + threadIdx.x; i < n4; i += gridDim.x * 256) {
        float4 v = in[i];
        __nv_bfloat16 h0, l0, h1, l1, h2, l2, h3, l3;
        split2(v.x, h0, l0); split2(v.y, h1, l1);
        split2(v.z, h2, l2); split2(v.w, h3, l3);
        __nv_bfloat162 a; a.x = h0; a.y = h1;
        __nv_bfloat162 b; b.x = h2; b.y = h3;
        oh2[i * 2] = a; oh2[i * 2 + 1] = b;
        a.x = l0; a.y = l1; b.x = l2; b.y = l3;
        ol2[i * 2] = a; ol2[i * 2 + 1] = b;
    }
}

// ---------------------------------------------------------------------------
// Transpose + split: in [R][C] fp32 -> out [C][R] bf16 hi/lo (batched)
// ---------------------------------------------------------------------------
__global__ __launch_bounds__(256)
void transpose_split(const float* __restrict__ in, __nv_bfloat16* __restrict__ oh,
                     __nv_bfloat16* __restrict__ ol, int R, int C,
                     long long sIn, long long sOut)
{
    __shared__ float t[32][33];
    in += (long long)blockIdx.z * sIn;
    oh += (long long)blockIdx.z * sOut;
    ol += (long long)blockIdx.z * sOut;
    const int c0 = blockIdx.x * 32, r0 = blockIdx.y * 32;
    const int tx = threadIdx.x, ty0 = threadIdx.y;   // blockDim (32, 8)
#pragma unroll
    for (int i = 0; i < 4; ++i) {
        int ty = ty0 + i * 8;
        t[ty][tx] = in[(long long)(r0 + ty) * C + c0 + tx];
    }
    __syncthreads();
#pragma unroll
    for (int i = 0; i < 4; ++i) {
        int ty = ty0 + i * 8;
        float v = t[tx][ty];                 // = in[r0+tx][c0+ty]
        __nv_bfloat16 h, l; split2(v, h, l);
        long long o = (long long)(c0 + ty) * R + r0 + tx;
        oh[o] = h; ol[o] = l;
    }
}

// ---------------------------------------------------------------------------
// In-place row softmax over 2048 cols + bf16 hi/lo split output
// ---------------------------------------------------------------------------
__global__ __launch_bounds__(256)
void softmax2048(float* __restrict__ data, __nv_bfloat16* __restrict__ alh,
                 __nv_bfloat16* __restrict__ all)
{
    float* row = data + (long long)blockIdx.x * 2048;
    __nv_bfloat162* hrow = reinterpret_cast<__nv_bfloat162*>(alh + (long long)blockIdx.x * 2048);
    __nv_bfloat162* lrow = reinterpret_cast<__nv_bfloat162*>(all + (long long)blockIdx.x * 2048);
    const int tid = threadIdx.x;

    float4 v0 = reinterpret_cast<float4*>(row)[tid];
    float4 v1 = reinterpret_cast<float4*>(row)[tid + 256];

    __shared__ float smr[8];
    __shared__ float bcast;

    float m = fmaxf(fmaxf(fmaxf(v0.x, v0.y), fmaxf(v0.z, v0.w)),
                    fmaxf(fmaxf(v1.x, v1.y), fmaxf(v1.z, v1.w)));
#pragma unroll
    for (int o = 16; o > 0; o >>= 1) m = fmaxf(m, __shfl_xor_sync(0xffffffffu, m, o));
    if ((tid & 31) == 0) smr[tid >> 5] = m;
    __syncthreads();
    if (tid == 0) {
        float t = smr[0];
#pragma unroll
        for (int i = 1; i < 8; ++i) t = fmaxf(t, smr[i]);
        bcast = t;
    }
    __syncthreads();
    m = bcast;
    __syncthreads();

    v0.x = __expf(v0.x - m); v0.y = __expf(v0.y - m);
    v0.z = __expf(v0.z - m); v0.w = __expf(v0.w - m);
    v1.x = __expf(v1.x - m); v1.y = __expf(v1.y - m);
    v1.z = __expf(v1.z - m); v1.w = __expf(v1.w - m);
    float s = (v0.x + v0.y) + (v0.z + v0.w) + (v1.x + v1.y) + (v1.z + v1.w);
#pragma unroll
    for (int o = 16; o > 0; o >>= 1) s += __shfl_xor_sync(0xffffffffu, s, o);
    if ((tid & 31) == 0) smr[tid >> 5] = s;
    __syncthreads();
    if (tid == 0) {
        float t = 0.0f;
#pragma unroll
        for (int i = 0; i < 8; ++i) t += smr[i];
        bcast = 1.0f / t;
    }
    __syncthreads();
    const float r = bcast;

    v0.x *= r; v0.y *= r; v0.z *= r; v0.w *= r;
    v1.x *= r; v1.y *= r; v1.z *= r; v1.w *= r;
    reinterpret_cast<float4*>(row)[tid]       = v0;
    reinterpret_cast<float4*>(row)[tid + 256] = v1;

    __nv_bfloat16 h0, l0, h1, l1;
    __nv_bfloat162 hv, lv;
    split2(v0.x, h0, l0); split2(v0.y, h1, l1);
    hv.x = h0; hv.y = h1; lv.x = l0; lv.y = l1;
    hrow[tid * 2] = hv; lrow[tid * 2] = lv;
    split2(v0.z, h0, l0); split2(v0.w, h1, l1);
    hv.x = h0; hv.y = h1; lv.x = l0; lv.y = l1;
    hrow[tid * 2 + 1] = hv; lrow[tid * 2 + 1] = lv;
    split2(v1.x, h0, l0); split2(v1.y, h1, l1);
    hv.x = h0; hv.y = h1; lv.x = l0; lv.y = l1;
    hrow[(256 + tid) * 2] = hv; lrow[(256 + tid) * 2] = lv;
    split2(v1.z, h0, l0); split2(v1.w, h1, l1);
    hv.x = h0; hv.y = h1; lv.x = l0; lv.y = l1;
    hrow[(256 + tid) * 2 + 1] = hv; lrow[(256 + tid) * 2 + 1] = lv;
}

// ---------------------------------------------------------------------------
extern "C" void kernel_launch(void* const* d_in, const int* in_sizes, int n_in,
                              void* d_out, int out_size)
{
    const float* dec = (const float*)d_in[0];   // [B, TQ, D]
    const float* enc = (const float*)d_in[1];   // [B, TK, D]
    const float* Wk  = (const float*)d_in[2];   // [D, D]
    const float* bia = (const float*)d_in[3];   // [D]
    if (n_in >= 4 && in_sizes[2] == D && in_sizes[3] == D * D) {
        const float* t = Wk; Wk = bia; bia = t;
    }

    float* out     = (float*)d_out;
    float* context = out;                          // B*TQ*D
    float* align   = out + (size_t)Bsz * TQ * D;   // B*TQ*TK (score scratch too)

    __nv_bfloat16 *dec_h, *dec_l, *enc_h, *enc_l, *encT_h, *encT_l;
    __nv_bfloat16 *Wt_h, *Wt_l, *key_h, *key_l, *al_h, *al_l;
    cudaGetSymbolAddress((void**)&dec_h,  g_dec_h);
    cudaGetSymbolAddress((void**)&dec_l,  g_dec_l);
    cudaGetSymbolAddress((void**)&enc_h,  g_enc_h);
    cudaGetSymbolAddress((void**)&enc_l,  g_enc_l);
    cudaGetSymbolAddress((void**)&encT_h, g_encT_h);
    cudaGetSymbolAddress((void**)&encT_l, g_encT_l);
    cudaGetSymbolAddress((void**)&Wt_h,   g_Wt_h);
    cudaGetSymbolAddress((void**)&Wt_l,   g_Wt_l);
    cudaGetSymbolAddress((void**)&key_h,  g_key_h);
    cudaGetSymbolAddress((void**)&key_l,  g_key_l);
    cudaGetSymbolAddress((void**)&al_h,   g_al_h);
    cudaGetSymbolAddress((void**)&al_l,   g_al_l);

    cudaFuncSetAttribute(gemm_bf16x3, cudaFuncAttributeMaxDynamicSharedMemorySize, SMEM_DYN);

    // 1) splits
    const int n4 = Bsz * TQ * D / 4;
    convert_split<<<4096, 256>>>((const float4*)dec, dec_h, dec_l, n4);
    convert_split<<<4096, 256>>>((const float4*)enc, enc_h, enc_l, n4);
    // 2) transposed splits (enc^T per batch, W^T)
    transpose_split<<<dim3(D / 32, TK / 32, Bsz), dim3(32, 8)>>>(
        enc, encT_h, encT_l, TK, D, (long long)TK * D, (long long)D * TK);
    transpose_split<<<dim3(D / 32, D / 32, 1), dim3(32, 8)>>>(
        Wk, Wt_h, Wt_l, D, D, 0LL, 0LL);

    // 3) keys = enc @ W + bias -> split bf16   (M=32768, N=1024, K=1024)
    gemm_bf16x3<<<dim3(D / 128, (Bsz * TK) / 128, 1), 256, SMEM_DYN>>>(
        enc_h, enc_l, Wt_h, Wt_l,
        nullptr, key_h, key_l, bia,
        D, D, 0LL, 0LL, 0LL);

    // 4) score[b] = dec[b] @ keys[b]^T -> fp32 into align region
    gemm_bf16x3<<<dim3(TK / 128, TQ / 128, Bsz), 256, SMEM_DYN>>>(
        dec_h, dec_l, key_h, key_l,
        align, nullptr, nullptr, nullptr,
        D, TK, (long long)TQ * D, (long long)TK * D, (long long)TQ * TK);

    // 5) softmax (in place) + bf16 split of alignment
    softmax2048<<<Bsz * TQ, 256>>>(align, al_h, al_l);

    // 6) context[b] = align[b] @ enc[b]   (B operand = encT, K=TK)
    gemm_bf16x3<<<dim3(D / 128, TQ / 128, Bsz), 256, SMEM_DYN>>>(
        al_h, al_l, encT_h, encT_l,
        context, nullptr, nullptr, nullptr,
        TK, D, (long long)TQ * TK, (long long)D * TK, (long long)TQ * D);
}

// round 4
// speedup vs baseline: 2.7990x; 1.0106x over previous
#include <cuda_runtime.h>
#include <cuda_bf16.h>
#include <cstdint>

// LuongAttention B=16, TQ=2048, TK=2048, D=1024
// out = [context (B*TQ*D fp32) | alignment (B*TQ*TK fp32)]
static constexpr int Bsz = 16;
static constexpr int TQ  = 2048;
static constexpr int TK  = 2048;
static constexpr int D   = 1024;

// ---------------- device scratch (allocation-free, 16B aligned for cp.async) --
__device__ __align__(16) __nv_bfloat16 g_dec_h[(size_t)Bsz * TQ * D];
__device__ __align__(16) __nv_bfloat16 g_dec_l[(size_t)Bsz * TQ * D];
__device__ __align__(16) __nv_bfloat16 g_enc_h[(size_t)Bsz * TK * D];
__device__ __align__(16) __nv_bfloat16 g_enc_l[(size_t)Bsz * TK * D];
__device__ __align__(16) __nv_bfloat16 g_encT_h[(size_t)Bsz * D * TK];
__device__ __align__(16) __nv_bfloat16 g_encT_l[(size_t)Bsz * D * TK];
__device__ __align__(16) __nv_bfloat16 g_Wt_h[(size_t)D * D];
__device__ __align__(16) __nv_bfloat16 g_Wt_l[(size_t)D * D];
__device__ __align__(16) __nv_bfloat16 g_key_h[(size_t)Bsz * TK * D];
__device__ __align__(16) __nv_bfloat16 g_key_l[(size_t)Bsz * TK * D];
__device__ __align__(16) __nv_bfloat16 g_al_h[(size_t)Bsz * TQ * TK];
__device__ __align__(16) __nv_bfloat16 g_al_l[(size_t)Bsz * TQ * TK];

// ---------------- helpers ----------------
__device__ __forceinline__ uint32_t smem_u32(const void* p) {
    uint32_t a;
    asm("{ .reg .u64 t; cvta.to.shared.u64 t, %1; cvt.u32.u64 %0, t; }"
        : "=r"(a) : "l"(p));
    return a;
}
__device__ __forceinline__ void cp_async16(uint32_t dst, const void* src) {
    asm volatile("{ .reg .u64 g; cvta.to.global.u64 g, %1;"
                 "  cp.async.cg.shared.global [%0], [g], 16; }"
                 :: "r"(dst), "l"(src) : "memory");
}
#define CP_COMMIT() asm volatile("cp.async.commit_group;" ::: "memory")
#define CP_WAIT1()  asm volatile("cp.async.wait_group 1;" ::: "memory")
#define CP_WAIT0()  asm volatile("cp.async.wait_group 0;" ::: "memory")

__device__ __forceinline__ void ldm_x4(uint32_t* r, uint32_t addr) {
    asm volatile("ldmatrix.sync.aligned.m8n8.x4.shared.b16 {%0,%1,%2,%3}, [%4];"
                 : "=r"(r[0]), "=r"(r[1]), "=r"(r[2]), "=r"(r[3]) : "r"(addr));
}
__device__ __forceinline__ void mma_bf16(float* c, const uint32_t* a, const uint32_t* b) {
    asm volatile("mma.sync.aligned.m16n8k16.row.col.f32.bf16.bf16.f32 "
                 "{%0,%1,%2,%3}, {%4,%5,%6,%7}, {%8,%9}, {%0,%1,%2,%3};"
                 : "+f"(c[0]), "+f"(c[1]), "+f"(c[2]), "+f"(c[3])
                 : "r"(a[0]), "r"(a[1]), "r"(a[2]), "r"(a[3]), "r"(b[0]), "r"(b[1]));
}
__device__ __forceinline__ void split2(float x, __nv_bfloat16& h, __nv_bfloat16& l) {
    h = __float2bfloat16_rn(x);
    l = __float2bfloat16_rn(x - __bfloat162float(h));
}

// smem geometry: padded stride 40 bf16 (80B) -> conflict-free ldmatrix
static constexpr int LDT = 40;
static constexpr int TILE_B  = 128 * LDT * 2;   // 10240 B per tile array
static constexpr int STAGE_B = 4 * TILE_B;      // Ah,Al,Bh,Bl
static constexpr int SMEM_DYN = 2 * STAGE_B;    // 81920 B double-buffered

// ---------------------------------------------------------------------------
// bf16x3 GEMM (emulated fp32) on mma.sync:  C[M,N] = A[M,K] * B[N,K]^T
// Tile 128x128, BK=32, 256 thr (8 warps, 2Mx4N, warp tile 64x32)
// grid = (N/128, M/128, batch)
// Inner loop is TERM-MAJOR: consecutive MMAs hit 4 distinct accumulators
// (dependency distance 4) instead of chaining 3 MMAs on one accumulator.
// ---------------------------------------------------------------------------
__global__ __launch_bounds__(256, 2)
void gemm_bf16x3(const __nv_bfloat16* __restrict__ Ah, const __nv_bfloat16* __restrict__ Al,
                 const __nv_bfloat16* __restrict__ Bh, const __nv_bfloat16* __restrict__ Bl,
                 float* __restrict__ Cf,
                 __nv_bfloat16* __restrict__ Chi, __nv_bfloat16* __restrict__ Clo,
                 const float* __restrict__ bias,
                 int K, int ldC,
                 long long sA, long long sB, long long sC)
{
    extern __shared__ __align__(128) char sm[];
    const uint32_t s0 = smem_u32(sm);

    const int tid  = threadIdx.x;
    const int wid  = tid >> 5;
    const int lane = tid & 31;
    const int wm   = wid & 1;     // 0..1  (M)
    const int wn   = wid >> 1;    // 0..3  (N)

    const long long zA = (long long)blockIdx.z * sA;
    const long long zB = (long long)blockIdx.z * sB;
    const __nv_bfloat16* pAh = Ah + zA + (long long)(blockIdx.y * 128) * K;
    const __nv_bfloat16* pAl = Al + zA + (long long)(blockIdx.y * 128) * K;
    const __nv_bfloat16* pBh = Bh + zB + (long long)(blockIdx.x * 128) * K;
    const __nv_bfloat16* pBl = Bl + zB + (long long)(blockIdx.x * 128) * K;

    // loader: 512 16B-chunks per array, 2 per thread
    const int lr0 = tid >> 2;           // row 0..63
    const int lc  = tid & 3;            // 16B chunk in row
    auto tileLoad = [&](int stage, int k0) {
        const uint32_t db = s0 + stage * STAGE_B;
#pragma unroll
        for (int i = 0; i < 2; ++i) {
            const int r = lr0 + i * 64;
            const uint32_t so = (uint32_t)(r * (LDT * 2) + lc * 16);
            const long long go = (long long)r * K + k0 + lc * 8;
            cp_async16(db + 0 * TILE_B + so, pAh + go);
            cp_async16(db + 1 * TILE_B + so, pAl + go);
            cp_async16(db + 2 * TILE_B + so, pBh + go);
            cp_async16(db + 3 * TILE_B + so, pBl + go);
        }
    };

    // lane-dependent ldmatrix base offsets (bytes)
    const uint32_t aOff = (uint32_t)(((wm * 64 + (lane & 15)) * LDT + ((lane >> 4) * 8)) * 2);
    const int bn = wn * 32 + (lane & 7) + ((lane & 16) >> 1);
    const uint32_t bOff = (uint32_t)((bn * LDT + (lane & 8)) * 2);

    float acc[4][4][4];
#pragma unroll
    for (int a = 0; a < 4; ++a)
#pragma unroll
        for (int b = 0; b < 4; ++b)
#pragma unroll
            for (int c = 0; c < 4; ++c) acc[a][b][c] = 0.0f;

    const int nk = K >> 5;
    tileLoad(0, 0);
    CP_COMMIT();

    for (int it = 0; it < nk; ++it) {
        if (it + 1 < nk) {
            tileLoad((it + 1) & 1, (it + 1) << 5);
            CP_COMMIT();
            CP_WAIT1();
        } else {
            CP_WAIT0();
        }
        __syncthreads();

        const uint32_t sb = s0 + (it & 1) * STAGE_B;
#pragma unroll
        for (int ks = 0; ks < 2; ++ks) {
            const uint32_t kso = ks * 32;            // 16 elements
            uint32_t fAh[4][4], fAl[4][4];
#pragma unroll
            for (int mt = 0; mt < 4; ++mt) {
                ldm_x4(fAh[mt], sb + 0 * TILE_B + aOff + kso + mt * 1280);
                ldm_x4(fAl[mt], sb + 1 * TILE_B + aOff + kso + mt * 1280);
            }
#pragma unroll
            for (int pp = 0; pp < 2; ++pp) {
                uint32_t fBh[4], fBl[4];
                ldm_x4(fBh, sb + 2 * TILE_B + bOff + kso + pp * 1280);
                ldm_x4(fBl, sb + 3 * TILE_B + bOff + kso + pp * 1280);
#pragma unroll
                for (int q = 0; q < 2; ++q) {
                    const int nt = pp * 2 + q;
                    // term-major: each group of 4 MMAs targets 4 distinct accs
#pragma unroll
                    for (int mt = 0; mt < 4; ++mt)
                        mma_bf16(acc[mt][nt], fAh[mt], fBh + q * 2);
#pragma unroll
                    for (int mt = 0; mt < 4; ++mt)
                        mma_bf16(acc[mt][nt], fAh[mt], fBl + q * 2);
#pragma unroll
                    for (int mt = 0; mt < 4; ++mt)
                        mma_bf16(acc[mt][nt], fAl[mt], fBh + q * 2);
                }
            }
        }
        __syncthreads();
    }

    // ---------------- epilogue ----------------
    const int rBase = blockIdx.y * 128 + wm * 64 + (lane >> 2);
    const int cBase = blockIdx.x * 128 + wn * 32 + (lane & 3) * 2;
    const long long zC = (long long)blockIdx.z * sC;

#pragma unroll
    for (int mt = 0; mt < 4; ++mt) {
#pragma unroll
        for (int h = 0; h < 2; ++h) {
            const int row = rBase + mt * 16 + h * 8;
#pragma unroll
            for (int nt = 0; nt < 4; ++nt) {
                const int col = cBase + nt * 8;
                float v0 = acc[mt][nt][h * 2 + 0];
                float v1 = acc[mt][nt][h * 2 + 1];
                if (bias) { v0 += bias[col]; v1 += bias[col + 1]; }
                const long long o = zC + (long long)row * ldC + col;
                if (Cf) {
                    float2 fv; fv.x = v0; fv.y = v1;
                    *(float2*)(Cf + o) = fv;
                }
                if (Chi) {
                    __nv_bfloat16 h0, l0, h1, l1;
                    split2(v0, h0, l0); split2(v1, h1, l1);
                    __nv_bfloat162 hv; hv.x = h0; hv.y = h1;
                    __nv_bfloat162 lv; lv.x = l0; lv.y = l1;
                    *(__nv_bfloat162*)(Chi + o) = hv;
                    *(__nv_bfloat162*)(Clo + o) = lv;
                }
            }
        }
    }
}

// ---------------------------------------------------------------------------
// Elementwise fp32 -> (hi, lo) bf16 split
// ---------------------------------------------------------------------------
__global__ __launch_bounds__(256)
void convert_split(const float4* __restrict__ in, __nv_bfloat16* __restrict__ oh,
                   __nv_bfloat16* __restrict__ ol, int n4)
{
    __nv_bfloat162* oh2 = reinterpret_cast<__nv_bfloat162*>(oh);
    __nv_bfloat162* ol2 = reinterpret_cast<__nv_bfloat162*>(ol);
    for (int i = blockIdx.x * 256 + threadIdx.x; i < n4; i += gridDim.x * 256) {
        float4 v = in[i];
        __nv_bfloat16 h0, l0, h1, l1, h2, l2, h3, l3;
        split2(v.x, h0, l0); split2(v.y, h1, l1);
        split2(v.z, h2, l2); split2(v.w, h3, l3);
        __nv_bfloat162 a; a.x = h0; a.y = h1;
        __nv_bfloat162 b; b.x = h2; b.y = h3;
        oh2[i * 2] = a; oh2[i * 2 + 1] = b;
        a.x = l0; a.y = l1; b.x = l2; b.y = l3;
        ol2[i * 2] = a; ol2[i * 2 + 1] = b;
    }
}

// ---------------------------------------------------------------------------
// Fused enc prep: read enc [TK][D] once per batch; write row-major hi/lo AND
// transposed [D][TK] hi/lo.
// blockDim (32,8), grid (D/32, TK/32, B)
// ---------------------------------------------------------------------------
__global__ __launch_bounds__(256)
void prep_enc(const float* __restrict__ in,
              __nv_bfloat16* __restrict__ rh, __nv_bfloat16* __restrict__ rl,
              __nv_bfloat16* __restrict__ th, __nv_bfloat16* __restrict__ tl)
{
    __shared__ float t[32][33];
    const long long zi = (long long)blockIdx.z * TK * D;
    const long long zo = (long long)blockIdx.z * D * TK;
    const int c0 = blockIdx.x * 32, r0 = blockIdx.y * 32;
    const int tx = threadIdx.x, ty0 = threadIdx.y;
#pragma unroll
    for (int i = 0; i < 4; ++i) {
        int ty = ty0 + i * 8;
        float v = in[zi + (long long)(r0 + ty) * D + c0 + tx];
        t[ty][tx] = v;
        __nv_bfloat16 h, l; split2(v, h, l);
        long long o = zi + (long long)(r0 + ty) * D + c0 + tx;
        rh[o] = h; rl[o] = l;
    }
    __syncthreads();
#pragma unroll
    for (int i = 0; i < 4; ++i) {
        int ty = ty0 + i * 8;
        float v = t[tx][ty];                 // = in[r0+tx][c0+ty]
        __nv_bfloat16 h, l; split2(v, h, l);
        long long o = zo + (long long)(c0 + ty) * TK + r0 + tx;
        th[o] = h; tl[o] = l;
    }
}

// ---------------------------------------------------------------------------
// Transpose + split (for W): in [R][C] fp32 -> out [C][R] bf16 hi/lo
// ---------------------------------------------------------------------------
__global__ __launch_bounds__(256)
void transpose_split(const float* __restrict__ in, __nv_bfloat16* __restrict__ oh,
                     __nv_bfloat16* __restrict__ ol, int R, int C)
{
    __shared__ float t[32][33];
    const int c0 = blockIdx.x * 32, r0 = blockIdx.y * 32;
    const int tx = threadIdx.x, ty0 = threadIdx.y;
#pragma unroll
    for (int i = 0; i < 4; ++i) {
        int ty = ty0 + i * 8;
        t[ty][tx] = in[(long long)(r0 + ty) * C + c0 + tx];
    }
    __syncthreads();
#pragma unroll
    for (int i = 0; i < 4; ++i) {
        int ty = ty0 + i * 8;
        float v = t[tx][ty];
        __nv_bfloat16 h, l; split2(v, h, l);
        long long o = (long long)(c0 + ty) * R + r0 + tx;
        oh[o] = h; ol[o] = l;
    }
}

// ---------------------------------------------------------------------------
// In-place row softmax over 2048 cols + bf16 hi/lo split output
// ---------------------------------------------------------------------------
__global__ __launch_bounds__(256)
void softmax2048(float* __restrict__ data, __nv_bfloat16* __restrict__ alh,
                 __nv_bfloat16* __restrict__ all)
{
    float* row = data + (long long)blockIdx.x * 2048;
    __nv_bfloat162* hrow = reinterpret_cast<__nv_bfloat162*>(alh + (long long)blockIdx.x * 2048);
    __nv_bfloat162* lrow = reinterpret_cast<__nv_bfloat162*>(all + (long long)blockIdx.x * 2048);
    const int tid = threadIdx.x;

    float4 v0 = reinterpret_cast<float4*>(row)[tid];
    float4 v1 = reinterpret_cast<float4*>(row)[tid + 256];

    __shared__ float smr[8];
    __shared__ float bcast;

    float m = fmaxf(fmaxf(fmaxf(v0.x, v0.y), fmaxf(v0.z, v0.w)),
                    fmaxf(fmaxf(v1.x, v1.y), fmaxf(v1.z, v1.w)));
#pragma unroll
    for (int o = 16; o > 0; o >>= 1) m = fmaxf(m, __shfl_xor_sync(0xffffffffu, m, o));
    if ((tid & 31) == 0) smr[tid >> 5] = m;
    __syncthreads();
    if (tid == 0) {
        float t = smr[0];
#pragma unroll
        for (int i = 1; i < 8; ++i) t = fmaxf(t, smr[i]);
        bcast = t;
    }
    __syncthreads();
    m = bcast;
    __syncthreads();

    v0.x = __expf(v0.x - m); v0.y = __expf(v0.y - m);
    v0.z = __expf(v0.z - m); v0.w = __expf(v0.w - m);
    v1.x = __expf(v1.x - m); v1.y = __expf(v1.y - m);
    v1.z = __expf(v1.z - m); v1.w = __expf(v1.w - m);
    float s = (v0.x + v0.y) + (v0.z + v0.w) + (v1.x + v1.y) + (v1.z + v1.w);
#pragma unroll
    for (int o = 16; o > 0; o >>= 1) s += __shfl_xor_sync(0xffffffffu, s, o);
    if ((tid & 31) == 0) smr[tid >> 5] = s;
    __syncthreads();
    if (tid == 0) {
        float t = 0.0f;
#pragma unroll
        for (int i = 0; i < 8; ++i) t += smr[i];
        bcast = 1.0f / t;
    }
    __syncthreads();
    const float r = bcast;

    v0.x *= r; v0.y *= r; v0.z *= r; v0.w *= r;
    v1.x *= r; v1.y *= r; v1.z *= r; v1.w *= r;
    reinterpret_cast<float4*>(row)[tid]       = v0;
    reinterpret_cast<float4*>(row)[tid + 256] = v1;

    __nv_bfloat16 h0, l0, h1, l1;
    __nv_bfloat162 hv, lv;
    split2(v0.x, h0, l0); split2(v0.y, h1, l1);
    hv.x = h0; hv.y = h1; lv.x = l0; lv.y = l1;
    hrow[tid * 2] = hv; lrow[tid * 2] = lv;
    split2(v0.z, h0, l0); split2(v0.w, h1, l1);
    hv.x = h0; hv.y = h1; lv.x = l0; lv.y = l1;
    hrow[tid * 2 + 1] = hv; lrow[tid * 2 + 1] = lv;
    split2(v1.x, h0, l0); split2(v1.y, h1, l1);
    hv.x = h0; hv.y = h1; lv.x = l0; lv.y = l1;
    hrow[(256 + tid) * 2] = hv; lrow[(256 + tid) * 2] = lv;
    split2(v1.z, h0, l0); split2(v1.w, h1, l1);
    hv.x = h0; hv.y = h1; lv.x = l0; lv.y = l1;
    hrow[(256 + tid) * 2 + 1] = hv; lrow[(256 + tid) * 2 + 1] = lv;
}

// ---------------------------------------------------------------------------
extern "C" void kernel_launch(void* const* d_in, const int* in_sizes, int n_in,
                              void* d_out, int out_size)
{
    const float* dec = (const float*)d_in[0];   // [B, TQ, D]
    const float* enc = (const float*)d_in[1];   // [B, TK, D]
    const float* Wk  = (const float*)d_in[2];   // [D, D]
    const float* bia = (const float*)d_in[3];   // [D]
    if (n_in >= 4 && in_sizes[2] == D && in_sizes[3] == D * D) {
        const float* t = Wk; Wk = bia; bia = t;
    }

    float* out     = (float*)d_out;
    float* context = out;                          // B*TQ*D
    float* align   = out + (size_t)Bsz * TQ * D;   // B*TQ*TK (score scratch too)

    __nv_bfloat16 *dec_h, *dec_l, *enc_h, *enc_l, *encT_h, *encT_l;
    __nv_bfloat16 *Wt_h, *Wt_l, *key_h, *key_l, *al_h, *al_l;
    cudaGetSymbolAddress((void**)&dec_h,  g_dec_h);
    cudaGetSymbolAddress((void**)&dec_l,  g_dec_l);
    cudaGetSymbolAddress((void**)&enc_h,  g_enc_h);
    cudaGetSymbolAddress((void**)&enc_l,  g_enc_l);
    cudaGetSymbolAddress((void**)&encT_h, g_encT_h);
    cudaGetSymbolAddress((void**)&encT_l, g_encT_l);
    cudaGetSymbolAddress((void**)&Wt_h,   g_Wt_h);
    cudaGetSymbolAddress((void**)&Wt_l,   g_Wt_l);
    cudaGetSymbolAddress((void**)&key_h,  g_key_h);
    cudaGetSymbolAddress((void**)&key_l,  g_key_l);
    cudaGetSymbolAddress((void**)&al_h,   g_al_h);
    cudaGetSymbolAddress((void**)&al_l,   g_al_l);

    cudaFuncSetAttribute(gemm_bf16x3, cudaFuncAttributeMaxDynamicSharedMemorySize, SMEM_DYN);

    // 1) prep: dec split; enc split + transpose fused; W transpose
    const int n4 = Bsz * TQ * D / 4;
    convert_split<<<4096, 256>>>((const float4*)dec, dec_h, dec_l, n4);
    prep_enc<<<dim3(D / 32, TK / 32, Bsz), dim3(32, 8)>>>(
        enc, enc_h, enc_l, encT_h, encT_l);
    transpose_split<<<dim3(D / 32, D / 32, 1), dim3(32, 8)>>>(
        Wk, Wt_h, Wt_l, D, D);

    // 2) keys = enc @ W + bias -> split bf16   (M=32768, N=1024, K=1024)
    gemm_bf16x3<<<dim3(D / 128, (Bsz * TK) / 128, 1), 256, SMEM_DYN>>>(
        enc_h, enc_l, Wt_h, Wt_l,
        nullptr, key_h, key_l, bia,
        D, D, 0LL, 0LL, 0LL);

    // 3) score[b] = dec[b] @ keys[b]^T -> fp32 into align region
    gemm_bf16x3<<<dim3(TK / 128, TQ / 128, Bsz), 256, SMEM_DYN>>>(
        dec_h, dec_l, key_h, key_l,
        align, nullptr, nullptr, nullptr,
        D, TK, (long long)TQ * D, (long long)TK * D, (long long)TQ * TK);

    // 4) softmax (in place) + bf16 split of alignment
    softmax2048<<<Bsz * TQ, 256>>>(align, al_h, al_l);

    // 5) context[b] = align[b] @ enc[b]   (B operand = encT, K=TK)
    gemm_bf16x3<<<dim3(D / 128, TQ / 128, Bsz), 256, SMEM_DYN>>>(
        al_h, al_l, encT_h, encT_l,
        context, nullptr, nullptr, nullptr,
        TK, D, (long long)TQ * TK, (long long)D * TK, (long long)TQ * D);
}

// round 5
// speedup vs baseline: 3.0425x; 1.0870x over previous
#include <cuda_runtime.h>
#include <cuda_bf16.h>
#include <cstdint>

// LuongAttention B=16, TQ=2048, TK=2048, D=1024
// out = [context (B*TQ*D fp32) | alignment (B*TQ*TK fp32)]
static constexpr int Bsz = 16;
static constexpr int TQ  = 2048;
static constexpr int TK  = 2048;
static constexpr int D   = 1024;

// ---------------- device scratch (allocation-free, 16B aligned for cp.async) --
__device__ __align__(16) __nv_bfloat16 g_dec_h[(size_t)Bsz * TQ * D];
__device__ __align__(16) __nv_bfloat16 g_dec_l[(size_t)Bsz * TQ * D];
__device__ __align__(16) __nv_bfloat16 g_enc_h[(size_t)Bsz * TK * D];
__device__ __align__(16) __nv_bfloat16 g_enc_l[(size_t)Bsz * TK * D];
__device__ __align__(16) __nv_bfloat16 g_encT_h[(size_t)Bsz * D * TK];
__device__ __align__(16) __nv_bfloat16 g_encT_l[(size_t)Bsz * D * TK];
__device__ __align__(16) __nv_bfloat16 g_Wt_h[(size_t)D * D];
__device__ __align__(16) __nv_bfloat16 g_Wt_l[(size_t)D * D];
__device__ __align__(16) __nv_bfloat16 g_key_h[(size_t)Bsz * TK * D];
__device__ __align__(16) __nv_bfloat16 g_key_l[(size_t)Bsz * TK * D];
__device__ __align__(16) __nv_bfloat16 g_al_h[(size_t)Bsz * TQ * TK];
__device__ __align__(16) __nv_bfloat16 g_al_l[(size_t)Bsz * TQ * TK];

// ---------------- helpers ----------------
__device__ __forceinline__ uint32_t smem_u32(const void* p) {
    uint32_t a;
    asm("{ .reg .u64 t; cvta.to.shared.u64 t, %1; cvt.u32.u64 %0, t; }"
        : "=r"(a) : "l"(p));
    return a;
}
__device__ __forceinline__ void cp_async16(uint32_t dst, const void* src) {
    asm volatile("{ .reg .u64 g; cvta.to.global.u64 g, %1;"
                 "  cp.async.cg.shared.global [%0], [g], 16; }"
                 :: "r"(dst), "l"(src) : "memory");
}
#define CP_COMMIT() asm volatile("cp.async.commit_group;" ::: "memory")
#define CP_WAIT1()  asm volatile("cp.async.wait_group 1;" ::: "memory")
#define CP_WAIT0()  asm volatile("cp.async.wait_group 0;" ::: "memory")

__device__ __forceinline__ void ldm_x4(uint32_t* r, uint32_t addr) {
    asm volatile("ldmatrix.sync.aligned.m8n8.x4.shared.b16 {%0,%1,%2,%3}, [%4];"
                 : "=r"(r[0]), "=r"(r[1]), "=r"(r[2]), "=r"(r[3]) : "r"(addr));
}
__device__ __forceinline__ void mma_bf16(float* c, const uint32_t* a, const uint32_t* b) {
    asm volatile("mma.sync.aligned.m16n8k16.row.col.f32.bf16.bf16.f32 "
                 "{%0,%1,%2,%3}, {%4,%5,%6,%7}, {%8,%9}, {%0,%1,%2,%3};"
                 : "+f"(c[0]), "+f"(c[1]), "+f"(c[2]), "+f"(c[3])
                 : "r"(a[0]), "r"(a[1]), "r"(a[2]), "r"(a[3]), "r"(b[0]), "r"(b[1]));
}
__device__ __forceinline__ void split2(float x, __nv_bfloat16& h, __nv_bfloat16& l) {
    h = __float2bfloat16_rn(x);
    l = __float2bfloat16_rn(x - __bfloat162float(h));
}

// smem geometry: padded stride 40 bf16 (80B) -> conflict-free ldmatrix
static constexpr int LDT = 40;
static constexpr int TILE_B  = 128 * LDT * 2;   // 10240 B per tile array
static constexpr int STAGE_B = 4 * TILE_B;      // Ah,Al,Bh,Bl
static constexpr int SMEM_DYN = 2 * STAGE_B;    // 81920 B double-buffered

// ---------------------------------------------------------------------------
// bf16x3 GEMM (emulated fp32) on mma.sync:  C[M,N] = A[M,K] * B[N,K]^T
// Tile 128x128, BK=32, 128 thr (4 warps, 2Mx2N, warp tile 64x64)
// -> MMA : ldmatrix ratio 6:1 (was 4:1), shifting the smem/tensor balance
// grid = (N/128, M/128, batch)
// ---------------------------------------------------------------------------
__global__ __launch_bounds__(128, 2)
void gemm_bf16x3(const __nv_bfloat16* __restrict__ Ah, const __nv_bfloat16* __restrict__ Al,
                 const __nv_bfloat16* __restrict__ Bh, const __nv_bfloat16* __restrict__ Bl,
                 float* __restrict__ Cf,
                 __nv_bfloat16* __restrict__ Chi, __nv_bfloat16* __restrict__ Clo,
                 const float* __restrict__ bias,
                 int K, int ldC,
                 long long sA, long long sB, long long sC)
{
    extern __shared__ __align__(128) char sm[];
    const uint32_t s0 = smem_u32(sm);

    const int tid  = threadIdx.x;
    const int wid  = tid >> 5;    // 0..3
    const int lane = tid & 31;
    const int wm   = wid & 1;     // 0..1  (M half)
    const int wn   = wid >> 1;    // 0..1  (N half)

    const long long zA = (long long)blockIdx.z * sA;
    const long long zB = (long long)blockIdx.z * sB;
    const __nv_bfloat16* pAh = Ah + zA + (long long)(blockIdx.y * 128) * K;
    const __nv_bfloat16* pAl = Al + zA + (long long)(blockIdx.y * 128) * K;
    const __nv_bfloat16* pBh = Bh + zB + (long long)(blockIdx.x * 128) * K;
    const __nv_bfloat16* pBl = Bl + zB + (long long)(blockIdx.x * 128) * K;

    // loader: 512 16B-chunks per array, 4 per thread (128 threads)
    const int lr0 = tid >> 2;           // row 0..31
    const int lc  = tid & 3;            // 16B chunk in row
    auto tileLoad = [&](int stage, int k0) {
        const uint32_t db = s0 + stage * STAGE_B;
#pragma unroll
        for (int i = 0; i < 4; ++i) {
            const int r = lr0 + i * 32;
            const uint32_t so = (uint32_t)(r * (LDT * 2) + lc * 16);
            const long long go = (long long)r * K + k0 + lc * 8;
            cp_async16(db + 0 * TILE_B + so, pAh + go);
            cp_async16(db + 1 * TILE_B + so, pAl + go);
            cp_async16(db + 2 * TILE_B + so, pBh + go);
            cp_async16(db + 3 * TILE_B + so, pBl + go);
        }
    };

    // lane-dependent ldmatrix base offsets (bytes)
    const uint32_t aOff = (uint32_t)(((wm * 64 + (lane & 15)) * LDT + ((lane >> 4) * 8)) * 2);
    const int bn = wn * 64 + (lane & 7) + ((lane & 16) >> 1);
    const uint32_t bOff = (uint32_t)((bn * LDT + (lane & 8)) * 2);

    float acc[4][8][4];
#pragma unroll
    for (int a = 0; a < 4; ++a)
#pragma unroll
        for (int b = 0; b < 8; ++b)
#pragma unroll
            for (int c = 0; c < 4; ++c) acc[a][b][c] = 0.0f;

    const int nk = K >> 5;
    tileLoad(0, 0);
    CP_COMMIT();

    for (int it = 0; it < nk; ++it) {
        if (it + 1 < nk) {
            tileLoad((it + 1) & 1, (it + 1) << 5);
            CP_COMMIT();
            CP_WAIT1();
        } else {
            CP_WAIT0();
        }
        __syncthreads();

        const uint32_t sb = s0 + (it & 1) * STAGE_B;
#pragma unroll
        for (int ks = 0; ks < 2; ++ks) {
            const uint32_t kso = ks * 32;            // 16 elements
            uint32_t fAh[4][4], fAl[4][4];
#pragma unroll
            for (int mt = 0; mt < 4; ++mt) {
                ldm_x4(fAh[mt], sb + 0 * TILE_B + aOff + kso + mt * 1280);
                ldm_x4(fAl[mt], sb + 1 * TILE_B + aOff + kso + mt * 1280);
            }
#pragma unroll
            for (int pp = 0; pp < 4; ++pp) {         // 4 x 16-col groups = 64 cols
                uint32_t fBh[4], fBl[4];
                ldm_x4(fBh, sb + 2 * TILE_B + bOff + kso + pp * 1280);
                ldm_x4(fBl, sb + 3 * TILE_B + bOff + kso + pp * 1280);
#pragma unroll
                for (int q = 0; q < 2; ++q) {
                    const int nt = pp * 2 + q;
                    // term-major: each group of 4 MMAs targets 4 distinct accs
#pragma unroll
                    for (int mt = 0; mt < 4; ++mt)
                        mma_bf16(acc[mt][nt], fAh[mt], fBh + q * 2);
#pragma unroll
                    for (int mt = 0; mt < 4; ++mt)
                        mma_bf16(acc[mt][nt], fAh[mt], fBl + q * 2);
#pragma unroll
                    for (int mt = 0; mt < 4; ++mt)
                        mma_bf16(acc[mt][nt], fAl[mt], fBh + q * 2);
                }
            }
        }
        __syncthreads();
    }

    // ---------------- epilogue ----------------
    const int rBase = blockIdx.y * 128 + wm * 64 + (lane >> 2);
    const int cBase = blockIdx.x * 128 + wn * 64 + (lane & 3) * 2;
    const long long zC = (long long)blockIdx.z * sC;

#pragma unroll
    for (int mt = 0; mt < 4; ++mt) {
#pragma unroll
        for (int h = 0; h < 2; ++h) {
            const int row = rBase + mt * 16 + h * 8;
#pragma unroll
            for (int nt = 0; nt < 8; ++nt) {
                const int col = cBase + nt * 8;
                float v0 = acc[mt][nt][h * 2 + 0];
                float v1 = acc[mt][nt][h * 2 + 1];
                if (bias) { v0 += bias[col]; v1 += bias[col + 1]; }
                const long long o = zC + (long long)row * ldC + col;
                if (Cf) {
                    float2 fv; fv.x = v0; fv.y = v1;
                    *(float2*)(Cf + o) = fv;
                }
                if (Chi) {
                    __nv_bfloat16 h0, l0, h1, l1;
                    split2(v0, h0, l0); split2(v1, h1, l1);
                    __nv_bfloat162 hv; hv.x = h0; hv.y = h1;
                    __nv_bfloat162 lv; lv.x = l0; lv.y = l1;
                    *(__nv_bfloat162*)(Chi + o) = hv;
                    *(__nv_bfloat162*)(Clo + o) = lv;
                }
            }
        }
    }
}

// ---------------------------------------------------------------------------
// Elementwise fp32 -> (hi, lo) bf16 split
// ---------------------------------------------------------------------------
__global__ __launch_bounds__(256)
void convert_split(const float4* __restrict__ in, __nv_bfloat16* __restrict__ oh,
                   __nv_bfloat16* __restrict__ ol, int n4)
{
    __nv_bfloat162* oh2 = reinterpret_cast<__nv_bfloat162*>(oh);
    __nv_bfloat162* ol2 = reinterpret_cast<__nv_bfloat162*>(ol);
    for (int i = blockIdx.x * 256 + threadIdx.x; i < n4; i += gridDim.x * 256) {
        float4 v = in[i];
        __nv_bfloat16 h0, l0, h1, l1, h2, l2, h3, l3;
        split2(v.x, h0, l0); split2(v.y, h1, l1);
        split2(v.z, h2, l2); split2(v.w, h3, l3);
        __nv_bfloat162 a; a.x = h0; a.y = h1;
        __nv_bfloat162 b; b.x = h2; b.y = h3;
        oh2[i * 2] = a; oh2[i * 2 + 1] = b;
        a.x = l0; a.y = l1; b.x = l2; b.y = l3;
        ol2[i * 2] = a; ol2[i * 2 + 1] = b;
    }
}

// ---------------------------------------------------------------------------
// Fused enc prep: read enc [TK][D] once per batch; write row-major hi/lo AND
// transposed [D][TK] hi/lo.  blockDim (32,8), grid (D/32, TK/32, B)
// ---------------------------------------------------------------------------
__global__ __launch_bounds__(256)
void prep_enc(const float* __restrict__ in,
              __nv_bfloat16* __restrict__ rh, __nv_bfloat16* __restrict__ rl,
              __nv_bfloat16* __restrict__ th, __nv_bfloat16* __restrict__ tl)
{
    __shared__ float t[32][33];
    const long long zi = (long long)blockIdx.z * TK * D;
    const long long zo = (long long)blockIdx.z * D * TK;
    const int c0 = blockIdx.x * 32, r0 = blockIdx.y * 32;
    const int tx = threadIdx.x, ty0 = threadIdx.y;
#pragma unroll
    for (int i = 0; i < 4; ++i) {
        int ty = ty0 + i * 8;
        float v = in[zi + (long long)(r0 + ty) * D + c0 + tx];
        t[ty][tx] = v;
        __nv_bfloat16 h, l; split2(v, h, l);
        long long o = zi + (long long)(r0 + ty) * D + c0 + tx;
        rh[o] = h; rl[o] = l;
    }
    __syncthreads();
#pragma unroll
    for (int i = 0; i < 4; ++i) {
        int ty = ty0 + i * 8;
        float v = t[tx][ty];                 // = in[r0+tx][c0+ty]
        __nv_bfloat16 h, l; split2(v, h, l);
        long long o = zo + (long long)(c0 + ty) * TK + r0 + tx;
        th[o] = h; tl[o] = l;
    }
}

// ---------------------------------------------------------------------------
// Transpose + split (for W): in [R][C] fp32 -> out [C][R] bf16 hi/lo
// ---------------------------------------------------------------------------
__global__ __launch_bounds__(256)
void transpose_split(const float* __restrict__ in, __nv_bfloat16* __restrict__ oh,
                     __nv_bfloat16* __restrict__ ol, int R, int C)
{
    __shared__ float t[32][33];
    const int c0 = blockIdx.x * 32, r0 = blockIdx.y * 32;
    const int tx = threadIdx.x, ty0 = threadIdx.y;
#pragma unroll
    for (int i = 0; i < 4; ++i) {
        int ty = ty0 + i * 8;
        t[ty][tx] = in[(long long)(r0 + ty) * C + c0 + tx];
    }
    __syncthreads();
#pragma unroll
    for (int i = 0; i < 4; ++i) {
        int ty = ty0 + i * 8;
        float v = t[tx][ty];
        __nv_bfloat16 h, l; split2(v, h, l);
        long long o = (long long)(c0 + ty) * R + r0 + tx;
        oh[o] = h; ol[o] = l;
    }
}

// ---------------------------------------------------------------------------
// In-place row softmax over 2048 cols + bf16 hi/lo split output
// ---------------------------------------------------------------------------
__global__ __launch_bounds__(256)
void softmax2048(float* __restrict__ data, __nv_bfloat16* __restrict__ alh,
                 __nv_bfloat16* __restrict__ all)
{
    float* row = data + (long long)blockIdx.x * 2048;
    __nv_bfloat162* hrow = reinterpret_cast<__nv_bfloat162*>(alh + (long long)blockIdx.x * 2048);
    __nv_bfloat162* lrow = reinterpret_cast<__nv_bfloat162*>(all + (long long)blockIdx.x * 2048);
    const int tid = threadIdx.x;

    float4 v0 = reinterpret_cast<float4*>(row)[tid];
    float4 v1 = reinterpret_cast<float4*>(row)[tid + 256];

    __shared__ float smr[8];
    __shared__ float bcast;

    float m = fmaxf(fmaxf(fmaxf(v0.x, v0.y), fmaxf(v0.z, v0.w)),
                    fmaxf(fmaxf(v1.x, v1.y), fmaxf(v1.z, v1.w)));
#pragma unroll
    for (int o = 16; o > 0; o >>= 1) m = fmaxf(m, __shfl_xor_sync(0xffffffffu, m, o));
    if ((tid & 31) == 0) smr[tid >> 5] = m;
    __syncthreads();
    if (tid == 0) {
        float t = smr[0];
#pragma unroll
        for (int i = 1; i < 8; ++i) t = fmaxf(t, smr[i]);
        bcast = t;
    }
    __syncthreads();
    m = bcast;
    __syncthreads();

    v0.x = __expf(v0.x - m); v0.y = __expf(v0.y - m);
    v0.z = __expf(v0.z - m); v0.w = __expf(v0.w - m);
    v1.x = __expf(v1.x - m); v1.y = __expf(v1.y - m);
    v1.z = __expf(v1.z - m); v1.w = __expf(v1.w - m);
    float s = (v0.x + v0.y) + (v0.z + v0.w) + (v1.x + v1.y) + (v1.z + v1.w);
#pragma unroll
    for (int o = 16; o > 0; o >>= 1) s += __shfl_xor_sync(0xffffffffu, s, o);
    if ((tid & 31) == 0) smr[tid >> 5] = s;
    __syncthreads();
    if (tid == 0) {
        float t = 0.0f;
#pragma unroll
        for (int i = 0; i < 8; ++i) t += smr[i];
        bcast = 1.0f / t;
    }
    __syncthreads();
    const float r = bcast;

    v0.x *= r; v0.y *= r; v0.z *= r; v0.w *= r;
    v1.x *= r; v1.y *= r; v1.z *= r; v1.w *= r;
    reinterpret_cast<float4*>(row)[tid]       = v0;
    reinterpret_cast<float4*>(row)[tid + 256] = v1;

    __nv_bfloat16 h0, l0, h1, l1;
    __nv_bfloat162 hv, lv;
    split2(v0.x, h0, l0); split2(v0.y, h1, l1);
    hv.x = h0; hv.y = h1; lv.x = l0; lv.y = l1;
    hrow[tid * 2] = hv; lrow[tid * 2] = lv;
    split2(v0.z, h0, l0); split2(v0.w, h1, l1);
    hv.x = h0; hv.y = h1; lv.x = l0; lv.y = l1;
    hrow[tid * 2 + 1] = hv; lrow[tid * 2 + 1] = lv;
    split2(v1.x, h0, l0); split2(v1.y, h1, l1);
    hv.x = h0; hv.y = h1; lv.x = l0; lv.y = l1;
    hrow[(256 + tid) * 2] = hv; lrow[(256 + tid) * 2] = lv;
    split2(v1.z, h0, l0); split2(v1.w, h1, l1);
    hv.x = h0; hv.y = h1; lv.x = l0; lv.y = l1;
    hrow[(256 + tid) * 2 + 1] = hv; lrow[(256 + tid) * 2 + 1] = lv;
}

// ---------------------------------------------------------------------------
extern "C" void kernel_launch(void* const* d_in, const int* in_sizes, int n_in,
                              void* d_out, int out_size)
{
    const float* dec = (const float*)d_in[0];   // [B, TQ, D]
    const float* enc = (const float*)d_in[1];   // [B, TK, D]
    const float* Wk  = (const float*)d_in[2];   // [D, D]
    const float* bia = (const float*)d_in[3];   // [D]
    if (n_in >= 4 && in_sizes[2] == D && in_sizes[3] == D * D) {
        const float* t = Wk; Wk = bia; bia = t;
    }

    float* out     = (float*)d_out;
    float* context = out;                          // B*TQ*D
    float* align   = out + (size_t)Bsz * TQ * D;   // B*TQ*TK (score scratch too)

    __nv_bfloat16 *dec_h, *dec_l, *enc_h, *enc_l, *encT_h, *encT_l;
    __nv_bfloat16 *Wt_h, *Wt_l, *key_h, *key_l, *al_h, *al_l;
    cudaGetSymbolAddress((void**)&dec_h,  g_dec_h);
    cudaGetSymbolAddress((void**)&dec_l,  g_dec_l);
    cudaGetSymbolAddress((void**)&enc_h,  g_enc_h);
    cudaGetSymbolAddress((void**)&enc_l,  g_enc_l);
    cudaGetSymbolAddress((void**)&encT_h, g_encT_h);
    cudaGetSymbolAddress((void**)&encT_l, g_encT_l);
    cudaGetSymbolAddress((void**)&Wt_h,   g_Wt_h);
    cudaGetSymbolAddress((void**)&Wt_l,   g_Wt_l);
    cudaGetSymbolAddress((void**)&key_h,  g_key_h);
    cudaGetSymbolAddress((void**)&key_l,  g_key_l);
    cudaGetSymbolAddress((void**)&al_h,   g_al_h);
    cudaGetSymbolAddress((void**)&al_l,   g_al_l);

    cudaFuncSetAttribute(gemm_bf16x3, cudaFuncAttributeMaxDynamicSharedMemorySize, SMEM_DYN);

    // 1) prep: dec split; enc split + transpose fused; W transpose
    const int n4 = Bsz * TQ * D / 4;
    convert_split<<<4096, 256>>>((const float4*)dec, dec_h, dec_l, n4);
    prep_enc<<<dim3(D / 32, TK / 32, Bsz), dim3(32, 8)>>>(
        enc, enc_h, enc_l, encT_h, encT_l);
    transpose_split<<<dim3(D / 32, D / 32, 1), dim3(32, 8)>>>(
        Wk, Wt_h, Wt_l, D, D);

    // 2) keys = enc @ W + bias -> split bf16   (M=32768, N=1024, K=1024)
    gemm_bf16x3<<<dim3(D / 128, (Bsz * TK) / 128, 1), 128, SMEM_DYN>>>(
        enc_h, enc_l, Wt_h, Wt_l,
        nullptr, key_h, key_l, bia,
        D, D, 0LL, 0LL, 0LL);

    // 3) score[b] = dec[b] @ keys[b]^T -> fp32 into align region
    gemm_bf16x3<<<dim3(TK / 128, TQ / 128, Bsz), 128, SMEM_DYN>>>(
        dec_h, dec_l, key_h, key_l,
        align, nullptr, nullptr, nullptr,
        D, TK, (long long)TQ * D, (long long)TK * D, (long long)TQ * TK);

    // 4) softmax (in place) + bf16 split of alignment
    softmax2048<<<Bsz * TQ, 256>>>(align, al_h, al_l);

    // 5) context[b] = align[b] @ enc[b]   (B operand = encT, K=TK)
    gemm_bf16x3<<<dim3(D / 128, TQ / 128, Bsz), 128, SMEM_DYN>>>(
        al_h, al_l, encT_h, encT_l,
        context, nullptr, nullptr, nullptr,
        TK, D, (long long)TQ * TK, (long long)D * TK, (long long)TQ * D);
}

// round 6
// speedup vs baseline: 3.3925x; 1.1150x over previous
#include <cuda_runtime.h>
#include <cuda_bf16.h>
#include <cstdint>

// LuongAttention B=16, TQ=2048, TK=2048, D=1024
// out = [context (B*TQ*D fp32) | alignment (B*TQ*TK fp32)]
static constexpr int Bsz = 16;
static constexpr int TQ  = 2048;
static constexpr int TK  = 2048;
static constexpr int D   = 1024;

// ---------------- device scratch (allocation-free, 16B aligned for cp.async) --
__device__ __align__(16) __nv_bfloat16 g_dec_h[(size_t)Bsz * TQ * D];
__device__ __align__(16) __nv_bfloat16 g_dec_l[(size_t)Bsz * TQ * D];
__device__ __align__(16) __nv_bfloat16 g_enc_h[(size_t)Bsz * TK * D];
__device__ __align__(16) __nv_bfloat16 g_enc_l[(size_t)Bsz * TK * D];
__device__ __align__(16) __nv_bfloat16 g_encT_h[(size_t)Bsz * D * TK];
__device__ __align__(16) __nv_bfloat16 g_encT_l[(size_t)Bsz * D * TK];
__device__ __align__(16) __nv_bfloat16 g_Wt_h[(size_t)D * D];
__device__ __align__(16) __nv_bfloat16 g_Wt_l[(size_t)D * D];
__device__ __align__(16) __nv_bfloat16 g_key_h[(size_t)Bsz * TK * D];
__device__ __align__(16) __nv_bfloat16 g_key_l[(size_t)Bsz * TK * D];
__device__ __align__(16) __nv_bfloat16 g_al_h[(size_t)Bsz * TQ * TK];
__device__ __align__(16) __nv_bfloat16 g_al_l[(size_t)Bsz * TQ * TK];

// ---------------- helpers ----------------
__device__ __forceinline__ uint32_t smem_u32(const void* p) {
    uint32_t a;
    asm("{ .reg .u64 t; cvta.to.shared.u64 t, %1; cvt.u32.u64 %0, t; }"
        : "=r"(a) : "l"(p));
    return a;
}
__device__ __forceinline__ void cp_async16(uint32_t dst, const void* src) {
    asm volatile("{ .reg .u64 g; cvta.to.global.u64 g, %1;"
                 "  cp.async.cg.shared.global [%0], [g], 16; }"
                 :: "r"(dst), "l"(src) : "memory");
}
#define CP_COMMIT() asm volatile("cp.async.commit_group;" ::: "memory")
#define CP_WAIT1()  asm volatile("cp.async.wait_group 1;" ::: "memory")
#define CP_WAIT0()  asm volatile("cp.async.wait_group 0;" ::: "memory")

__device__ __forceinline__ void ldm_x4(uint32_t* r, uint32_t addr) {
    asm volatile("ldmatrix.sync.aligned.m8n8.x4.shared.b16 {%0,%1,%2,%3}, [%4];"
                 : "=r"(r[0]), "=r"(r[1]), "=r"(r[2]), "=r"(r[3]) : "r"(addr));
}
__device__ __forceinline__ void mma_bf16(float* c, const uint32_t* a, const uint32_t* b) {
    asm volatile("mma.sync.aligned.m16n8k16.row.col.f32.bf16.bf16.f32 "
                 "{%0,%1,%2,%3}, {%4,%5,%6,%7}, {%8,%9}, {%0,%1,%2,%3};"
                 : "+f"(c[0]), "+f"(c[1]), "+f"(c[2]), "+f"(c[3])
                 : "r"(a[0]), "r"(a[1]), "r"(a[2]), "r"(a[3]), "r"(b[0]), "r"(b[1]));
}
__device__ __forceinline__ void split2(float x, __nv_bfloat16& h, __nv_bfloat16& l) {
    h = __float2bfloat16_rn(x);
    l = __float2bfloat16_rn(x - __bfloat162float(h));
}

// smem geometry: 128 rows x 64B (32 bf16), XOR swizzle -> no padding
// chunk' = chunk ^ ((row>>1)&3); 8-row atoms hit 8 distinct 4-bank groups.
static constexpr int TILE_B  = 128 * 64;        // 8192 B per tile array
static constexpr int STAGE_B = 4 * TILE_B;      // Ah,Al,Bh,Bl = 32768 B
static constexpr int NSTAGE  = 3;
static constexpr int SMEM_DYN = NSTAGE * STAGE_B;  // 98304 B

__device__ __forceinline__ uint32_t sw_addr(int row, int chunk) {
    return (uint32_t)(row * 64 + ((chunk ^ ((row >> 1) & 3)) << 4));
}

// ---------------------------------------------------------------------------
// bf16x3 GEMM (emulated fp32) on mma.sync:  C[M,N] = A[M,K] * B[N,K]^T
// Tile 128x128, BK=32, 128 thr (4 warps, 2Mx2N, warp tile 64x64)
// 3-stage cp.async pipeline, ONE __syncthreads per K-iteration.
// grid = (N/128, M/128, batch)
// ---------------------------------------------------------------------------
__global__ __launch_bounds__(128, 2)
void gemm_bf16x3(const __nv_bfloat16* __restrict__ Ah, const __nv_bfloat16* __restrict__ Al,
                 const __nv_bfloat16* __restrict__ Bh, const __nv_bfloat16* __restrict__ Bl,
                 float* __restrict__ Cf,
                 __nv_bfloat16* __restrict__ Chi, __nv_bfloat16* __restrict__ Clo,
                 const float* __restrict__ bias,
                 int K, int ldC,
                 long long sA, long long sB, long long sC)
{
    extern __shared__ __align__(128) char sm[];
    const uint32_t s0 = smem_u32(sm);

    const int tid  = threadIdx.x;
    const int wid  = tid >> 5;    // 0..3
    const int lane = tid & 31;
    const int wm   = wid & 1;     // M half
    const int wn   = wid >> 1;    // N half

    const long long zA = (long long)blockIdx.z * sA;
    const long long zB = (long long)blockIdx.z * sB;
    const __nv_bfloat16* pAh = Ah + zA + (long long)(blockIdx.y * 128) * K;
    const __nv_bfloat16* pAl = Al + zA + (long long)(blockIdx.y * 128) * K;
    const __nv_bfloat16* pBh = Bh + zB + (long long)(blockIdx.x * 128) * K;
    const __nv_bfloat16* pBl = Bl + zB + (long long)(blockIdx.x * 128) * K;

    // loader: 512 16B-chunks per array, 4 per thread (128 threads)
    const int lr0 = tid >> 2;           // row 0..31
    const int lc  = tid & 3;            // chunk 0..3
    auto tileLoad = [&](int stage, int k0) {
        const uint32_t db = s0 + stage * STAGE_B;
#pragma unroll
        for (int i = 0; i < 4; ++i) {
            const int r = lr0 + i * 32;
            const uint32_t so = sw_addr(r, lc);
            const long long go = (long long)r * K + k0 + lc * 8;
            cp_async16(db + 0 * TILE_B + so, pAh + go);
            cp_async16(db + 1 * TILE_B + so, pAl + go);
            cp_async16(db + 2 * TILE_B + so, pBh + go);
            cp_async16(db + 3 * TILE_B + so, pBl + go);
        }
        CP_COMMIT();
    };

    // ldmatrix lane geometry
    const int rowA0 = wm * 64 + (lane & 15);         // + mt*16
    const int hiA   = lane >> 4;                     // chunk half (0/1)
    const int rowB0 = wn * 64 + (lane & 7) + ((lane & 16) >> 1);  // + pp*16
    const int hiB   = (lane & 8) >> 3;               // chunk half (0/1)

    float acc[4][8][4];
#pragma unroll
    for (int a = 0; a < 4; ++a)
#pragma unroll
        for (int b = 0; b < 8; ++b)
#pragma unroll
            for (int c = 0; c < 4; ++c) acc[a][b][c] = 0.0f;

    const int nk = K >> 5;
    tileLoad(0, 0);
    tileLoad(1, 32);

    int stage = 0;
    for (int it = 0; it < nk; ++it) {
        if (it + 2 < nk) { CP_WAIT1(); } else { CP_WAIT0(); }
        __syncthreads();
        if (it + 2 < nk) {
            int ns = stage + 2; if (ns >= NSTAGE) ns -= NSTAGE;
            tileLoad(ns, (it + 2) << 5);
        }

        const uint32_t sb = s0 + stage * STAGE_B;
#pragma unroll
        for (int ks = 0; ks < 2; ++ks) {
            uint32_t fAh[4][4], fAl[4][4];
#pragma unroll
            for (int mt = 0; mt < 4; ++mt) {
                const int r = rowA0 + mt * 16;
                const uint32_t ao = sw_addr(r, hiA + ks * 2);
                ldm_x4(fAh[mt], sb + 0 * TILE_B + ao);
                ldm_x4(fAl[mt], sb + 1 * TILE_B + ao);
            }
#pragma unroll
            for (int pp = 0; pp < 4; ++pp) {         // 4 x 16-col groups
                const int rb = rowB0 + pp * 16;
                const uint32_t bo = sw_addr(rb, hiB + ks * 2);
                uint32_t fBh[4], fBl[4];
                ldm_x4(fBh, sb + 2 * TILE_B + bo);
                ldm_x4(fBl, sb + 3 * TILE_B + bo);
#pragma unroll
                for (int q = 0; q < 2; ++q) {
                    const int nt = pp * 2 + q;
                    // term-major: 4 distinct accumulators per MMA group
#pragma unroll
                    for (int mt = 0; mt < 4; ++mt)
                        mma_bf16(acc[mt][nt], fAh[mt], fBh + q * 2);
#pragma unroll
                    for (int mt = 0; mt < 4; ++mt)
                        mma_bf16(acc[mt][nt], fAh[mt], fBl + q * 2);
#pragma unroll
                    for (int mt = 0; mt < 4; ++mt)
                        mma_bf16(acc[mt][nt], fAl[mt], fBh + q * 2);
                }
            }
        }
        if (++stage >= NSTAGE) stage = 0;
    }

    // ---------------- epilogue ----------------
    const int rBase = blockIdx.y * 128 + wm * 64 + (lane >> 2);
    const int cBase = blockIdx.x * 128 + wn * 64 + (lane & 3) * 2;
    const long long zC = (long long)blockIdx.z * sC;

#pragma unroll
    for (int mt = 0; mt < 4; ++mt) {
#pragma unroll
        for (int h = 0; h < 2; ++h) {
            const int row = rBase + mt * 16 + h * 8;
#pragma unroll
            for (int nt = 0; nt < 8; ++nt) {
                const int col = cBase + nt * 8;
                float v0 = acc[mt][nt][h * 2 + 0];
                float v1 = acc[mt][nt][h * 2 + 1];
                if (bias) { v0 += bias[col]; v1 += bias[col + 1]; }
                const long long o = zC + (long long)row * ldC + col;
                if (Cf) {
                    float2 fv; fv.x = v0; fv.y = v1;
                    *(float2*)(Cf + o) = fv;
                }
                if (Chi) {
                    __nv_bfloat16 h0, l0, h1, l1;
                    split2(v0, h0, l0); split2(v1, h1, l1);
                    __nv_bfloat162 hv; hv.x = h0; hv.y = h1;
                    __nv_bfloat162 lv; lv.x = l0; lv.y = l1;
                    *(__nv_bfloat162*)(Chi + o) = hv;
                    *(__nv_bfloat162*)(Clo + o) = lv;
                }
            }
        }
    }
}

// ---------------------------------------------------------------------------
// Elementwise fp32 -> (hi, lo) bf16 split
// ---------------------------------------------------------------------------
__global__ __launch_bounds__(256)
void convert_split(const float4* __restrict__ in, __nv_bfloat16* __restrict__ oh,
                   __nv_bfloat16* __restrict__ ol, int n4)
{
    __nv_bfloat162* oh2 = reinterpret_cast<__nv_bfloat162*>(oh);
    __nv_bfloat162* ol2 = reinterpret_cast<__nv_bfloat162*>(ol);
    for (int i = blockIdx.x * 256 + threadIdx.x; i < n4; i += gridDim.x * 256) {
        float4 v = in[i];
        __nv_bfloat16 h0, l0, h1, l1, h2, l2, h3, l3;
        split2(v.x, h0, l0); split2(v.y, h1, l1);
        split2(v.z, h2, l2); split2(v.w, h3, l3);
        __nv_bfloat162 a; a.x = h0; a.y = h1;
        __nv_bfloat162 b; b.x = h2; b.y = h3;
        oh2[i * 2] = a; oh2[i * 2 + 1] = b;
        a.x = l0; a.y = l1; b.x = l2; b.y = l3;
        ol2[i * 2] = a; ol2[i * 2 + 1] = b;
    }
}

// ---------------------------------------------------------------------------
// Fused enc prep: read enc [TK][D] once per batch; write row-major hi/lo AND
// transposed [D][TK] hi/lo.  blockDim (32,8), grid (D/32, TK/32, B)
// ---------------------------------------------------------------------------
__global__ __launch_bounds__(256)
void prep_enc(const float* __restrict__ in,
              __nv_bfloat16* __restrict__ rh, __nv_bfloat16* __restrict__ rl,
              __nv_bfloat16* __restrict__ th, __nv_bfloat16* __restrict__ tl)
{
    __shared__ float t[32][33];
    const long long zi = (long long)blockIdx.z * TK * D;
    const long long zo = (long long)blockIdx.z * D * TK;
    const int c0 = blockIdx.x * 32, r0 = blockIdx.y * 32;
    const int tx = threadIdx.x, ty0 = threadIdx.y;
#pragma unroll
    for (int i = 0; i < 4; ++i) {
        int ty = ty0 + i * 8;
        float v = in[zi + (long long)(r0 + ty) * D + c0 + tx];
        t[ty][tx] = v;
        __nv_bfloat16 h, l; split2(v, h, l);
        long long o = zi + (long long)(r0 + ty) * D + c0 + tx;
        rh[o] = h; rl[o] = l;
    }
    __syncthreads();
#pragma unroll
    for (int i = 0; i < 4; ++i) {
        int ty = ty0 + i * 8;
        float v = t[tx][ty];                 // = in[r0+tx][c0+ty]
        __nv_bfloat16 h, l; split2(v, h, l);
        long long o = zo + (long long)(c0 + ty) * TK + r0 + tx;
        th[o] = h; tl[o] = l;
    }
}

// ---------------------------------------------------------------------------
// Transpose + split (for W): in [R][C] fp32 -> out [C][R] bf16 hi/lo
// ---------------------------------------------------------------------------
__global__ __launch_bounds__(256)
void transpose_split(const float* __restrict__ in, __nv_bfloat16* __restrict__ oh,
                     __nv_bfloat16* __restrict__ ol, int R, int C)
{
    __shared__ float t[32][33];
    const int c0 = blockIdx.x * 32, r0 = blockIdx.y * 32;
    const int tx = threadIdx.x, ty0 = threadIdx.y;
#pragma unroll
    for (int i = 0; i < 4; ++i) {
        int ty = ty0 + i * 8;
        t[ty][tx] = in[(long long)(r0 + ty) * C + c0 + tx];
    }
    __syncthreads();
#pragma unroll
    for (int i = 0; i < 4; ++i) {
        int ty = ty0 + i * 8;
        float v = t[tx][ty];
        __nv_bfloat16 h, l; split2(v, h, l);
        long long o = (long long)(c0 + ty) * R + r0 + tx;
        oh[o] = h; ol[o] = l;
    }
}

// ---------------------------------------------------------------------------
// In-place row softmax over 2048 cols + bf16 hi/lo split output
// ---------------------------------------------------------------------------
__global__ __launch_bounds__(256)
void softmax2048(float* __restrict__ data, __nv_bfloat16* __restrict__ alh,
                 __nv_bfloat16* __restrict__ all)
{
    float* row = data + (long long)blockIdx.x * 2048;
    __nv_bfloat162* hrow = reinterpret_cast<__nv_bfloat162*>(alh + (long long)blockIdx.x * 2048);
    __nv_bfloat162* lrow = reinterpret_cast<__nv_bfloat162*>(all + (long long)blockIdx.x * 2048);
    const int tid = threadIdx.x;

    float4 v0 = reinterpret_cast<float4*>(row)[tid];
    float4 v1 = reinterpret_cast<float4*>(row)[tid + 256];

    __shared__ float smr[8];
    __shared__ float bcast;

    float m = fmaxf(fmaxf(fmaxf(v0.x, v0.y), fmaxf(v0.z, v0.w)),
                    fmaxf(fmaxf(v1.x, v1.y), fmaxf(v1.z, v1.w)));
#pragma unroll
    for (int o = 16; o > 0; o >>= 1) m = fmaxf(m, __shfl_xor_sync(0xffffffffu, m, o));
    if ((tid & 31) == 0) smr[tid >> 5] = m;
    __syncthreads();
    if (tid == 0) {
        float t = smr[0];
#pragma unroll
        for (int i = 1; i < 8; ++i) t = fmaxf(t, smr[i]);
        bcast = t;
    }
    __syncthreads();
    m = bcast;
    __syncthreads();

    v0.x = __expf(v0.x - m); v0.y = __expf(v0.y - m);
    v0.z = __expf(v0.z - m); v0.w = __expf(v0.w - m);
    v1.x = __expf(v1.x - m); v1.y = __expf(v1.y - m);
    v1.z = __expf(v1.z - m); v1.w = __expf(v1.w - m);
    float s = (v0.x + v0.y) + (v0.z + v0.w) + (v1.x + v1.y) + (v1.z + v1.w);
#pragma unroll
    for (int o = 16; o > 0; o >>= 1) s += __shfl_xor_sync(0xffffffffu, s, o);
    if ((tid & 31) == 0) smr[tid >> 5] = s;
    __syncthreads();
    if (tid == 0) {
        float t = 0.0f;
#pragma unroll
        for (int i = 0; i < 8; ++i) t += smr[i];
        bcast = 1.0f / t;
    }
    __syncthreads();
    const float r = bcast;

    v0.x *= r; v0.y *= r; v0.z *= r; v0.w *= r;
    v1.x *= r; v1.y *= r; v1.z *= r; v1.w *= r;
    reinterpret_cast<float4*>(row)[tid]       = v0;
    reinterpret_cast<float4*>(row)[tid + 256] = v1;

    __nv_bfloat16 h0, l0, h1, l1;
    __nv_bfloat162 hv, lv;
    split2(v0.x, h0, l0); split2(v0.y, h1, l1);
    hv.x = h0; hv.y = h1; lv.x = l0; lv.y = l1;
    hrow[tid * 2] = hv; lrow[tid * 2] = lv;
    split2(v0.z, h0, l0); split2(v0.w, h1, l1);
    hv.x = h0; hv.y = h1; lv.x = l0; lv.y = l1;
    hrow[tid * 2 + 1] = hv; lrow[tid * 2 + 1] = lv;
    split2(v1.x, h0, l0); split2(v1.y, h1, l1);
    hv.x = h0; hv.y = h1; lv.x = l0; lv.y = l1;
    hrow[(256 + tid) * 2] = hv; lrow[(256 + tid) * 2] = lv;
    split2(v1.z, h0, l0); split2(v1.w, h1, l1);
    hv.x = h0; hv.y = h1; lv.x = l0; lv.y = l1;
    hrow[(256 + tid) * 2 + 1] = hv; lrow[(256 + tid) * 2 + 1] = lv;
}

// ---------------------------------------------------------------------------
extern "C" void kernel_launch(void* const* d_in, const int* in_sizes, int n_in,
                              void* d_out, int out_size)
{
    const float* dec = (const float*)d_in[0];   // [B, TQ, D]
    const float* enc = (const float*)d_in[1];   // [B, TK, D]
    const float* Wk  = (const float*)d_in[2];   // [D, D]
    const float* bia = (const float*)d_in[3];   // [D]
    if (n_in >= 4 && in_sizes[2] == D && in_sizes[3] == D * D) {
        const float* t = Wk; Wk = bia; bia = t;
    }

    float* out     = (float*)d_out;
    float* context = out;                          // B*TQ*D
    float* align   = out + (size_t)Bsz * TQ * D;   // B*TQ*TK (score scratch too)

    __nv_bfloat16 *dec_h, *dec_l, *enc_h, *enc_l, *encT_h, *encT_l;
    __nv_bfloat16 *Wt_h, *Wt_l, *key_h, *key_l, *al_h, *al_l;
    cudaGetSymbolAddress((void**)&dec_h,  g_dec_h);
    cudaGetSymbolAddress((void**)&dec_l,  g_dec_l);
    cudaGetSymbolAddress((void**)&enc_h,  g_enc_h);
    cudaGetSymbolAddress((void**)&enc_l,  g_enc_l);
    cudaGetSymbolAddress((void**)&encT_h, g_encT_h);
    cudaGetSymbolAddress((void**)&encT_l, g_encT_l);
    cudaGetSymbolAddress((void**)&Wt_h,   g_Wt_h);
    cudaGetSymbolAddress((void**)&Wt_l,   g_Wt_l);
    cudaGetSymbolAddress((void**)&key_h,  g_key_h);
    cudaGetSymbolAddress((void**)&key_l,  g_key_l);
    cudaGetSymbolAddress((void**)&al_h,   g_al_h);
    cudaGetSymbolAddress((void**)&al_l,   g_al_l);

    cudaFuncSetAttribute(gemm_bf16x3, cudaFuncAttributeMaxDynamicSharedMemorySize, SMEM_DYN);

    // 1) prep: dec split; enc split + transpose fused; W transpose
    const int n4 = Bsz * TQ * D / 4;
    convert_split<<<4096, 256>>>((const float4*)dec, dec_h, dec_l, n4);
    prep_enc<<<dim3(D / 32, TK / 32, Bsz), dim3(32, 8)>>>(
        enc, enc_h, enc_l, encT_h, encT_l);
    transpose_split<<<dim3(D / 32, D / 32, 1), dim3(32, 8)>>>(
        Wk, Wt_h, Wt_l, D, D);

    // 2) keys = enc @ W + bias -> split bf16   (M=32768, N=1024, K=1024)
    gemm_bf16x3<<<dim3(D / 128, (Bsz * TK) / 128, 1), 128, SMEM_DYN>>>(
        enc_h, enc_l, Wt_h, Wt_l,
        nullptr, key_h, key_l, bia,
        D, D, 0LL, 0LL, 0LL);

    // 3) score[b] = dec[b] @ keys[b]^T -> fp32 into align region
    gemm_bf16x3<<<dim3(TK / 128, TQ / 128, Bsz), 128, SMEM_DYN>>>(
        dec_h, dec_l, key_h, key_l,
        align, nullptr, nullptr, nullptr,
        D, TK, (long long)TQ * D, (long long)TK * D, (long long)TQ * TK);

    // 4) softmax (in place) + bf16 split of alignment
    softmax2048<<<Bsz * TQ, 256>>>(align, al_h, al_l);

    // 5) context[b] = align[b] @ enc[b]   (B operand = encT, K=TK)
    gemm_bf16x3<<<dim3(D / 128, TQ / 128, Bsz), 128, SMEM_DYN>>>(
        al_h, al_l, encT_h, encT_l,
        context, nullptr, nullptr, nullptr,
        TK, D, (long long)TQ * TK, (long long)D * TK, (long long)TQ * D);
}

// round 7
// speedup vs baseline: 3.8356x; 1.1306x over previous
#include <cuda_runtime.h>
#include <cuda_bf16.h>
#include <cuda_fp16.h>
#include <cstdint>

// LuongAttention B=16, TQ=2048, TK=2048, D=1024
// out = [context (B*TQ*D fp32) | alignment (B*TQ*TK fp32)]
static constexpr int Bsz = 16;
static constexpr int TQ  = 2048;
static constexpr int TK  = 2048;
static constexpr int D   = 1024;

// ---------------- device scratch (allocation-free, 16B aligned) ----------------
__device__ __align__(16) __nv_bfloat16 g_dec_h[(size_t)Bsz * TQ * D];
__device__ __align__(16) __nv_bfloat16 g_dec_l[(size_t)Bsz * TQ * D];
__device__ __align__(16) __nv_bfloat16 g_enc_h[(size_t)Bsz * TK * D];
__device__ __align__(16) __nv_bfloat16 g_enc_l[(size_t)Bsz * TK * D];
__device__ __align__(16) __half        g_encT_h[(size_t)Bsz * D * TK];   // fp16 hi
__device__ __align__(16) __half        g_encT_l[(size_t)Bsz * D * TK];   // fp16 lo
__device__ __align__(16) __nv_bfloat16 g_Wt_h[(size_t)D * D];
__device__ __align__(16) __nv_bfloat16 g_Wt_l[(size_t)D * D];
__device__ __align__(16) __nv_bfloat16 g_key_h[(size_t)Bsz * TK * D];
__device__ __align__(16) __nv_bfloat16 g_key_l[(size_t)Bsz * TK * D];
__device__ __align__(16) __half        g_al_f16[(size_t)Bsz * TQ * TK];  // fp16 alignment

// ---------------- helpers ----------------
__device__ __forceinline__ uint32_t smem_u32(const void* p) {
    uint32_t a;
    asm("{ .reg .u64 t; cvta.to.shared.u64 t, %1; cvt.u32.u64 %0, t; }"
        : "=r"(a) : "l"(p));
    return a;
}
__device__ __forceinline__ void cp_async16(uint32_t dst, const void* src) {
    asm volatile("{ .reg .u64 g; cvta.to.global.u64 g, %1;"
                 "  cp.async.cg.shared.global [%0], [g], 16; }"
                 :: "r"(dst), "l"(src) : "memory");
}
#define CP_COMMIT() asm volatile("cp.async.commit_group;" ::: "memory")
#define CP_WAIT1()  asm volatile("cp.async.wait_group 1;" ::: "memory")
#define CP_WAIT0()  asm volatile("cp.async.wait_group 0;" ::: "memory")

__device__ __forceinline__ void ldm_x4(uint32_t* r, uint32_t addr) {
    asm volatile("ldmatrix.sync.aligned.m8n8.x4.shared.b16 {%0,%1,%2,%3}, [%4];"
                 : "=r"(r[0]), "=r"(r[1]), "=r"(r[2]), "=r"(r[3]) : "r"(addr));
}
__device__ __forceinline__ void mma_bf16(float* c, const uint32_t* a, const uint32_t* b) {
    asm volatile("mma.sync.aligned.m16n8k16.row.col.f32.bf16.bf16.f32 "
                 "{%0,%1,%2,%3}, {%4,%5,%6,%7}, {%8,%9}, {%0,%1,%2,%3};"
                 : "+f"(c[0]), "+f"(c[1]), "+f"(c[2]), "+f"(c[3])
                 : "r"(a[0]), "r"(a[1]), "r"(a[2]), "r"(a[3]), "r"(b[0]), "r"(b[1]));
}
__device__ __forceinline__ void mma_fp16(float* c, const uint32_t* a, const uint32_t* b) {
    asm volatile("mma.sync.aligned.m16n8k16.row.col.f32.f16.f16.f32 "
                 "{%0,%1,%2,%3}, {%4,%5,%6,%7}, {%8,%9}, {%0,%1,%2,%3};"
                 : "+f"(c[0]), "+f"(c[1]), "+f"(c[2]), "+f"(c[3])
                 : "r"(a[0]), "r"(a[1]), "r"(a[2]), "r"(a[3]), "r"(b[0]), "r"(b[1]));
}
__device__ __forceinline__ void split2(float x, __nv_bfloat16& h, __nv_bfloat16& l) {
    h = __float2bfloat16_rn(x);
    l = __float2bfloat16_rn(x - __bfloat162float(h));
}
__device__ __forceinline__ void split2h(float x, __half& h, __half& l) {
    h = __float2half_rn(x);
    l = __float2half_rn(x - __half2float(h));
}

// smem geometry: 128 rows x 64B (32 elems), XOR swizzle -> no padding
static constexpr int TILE_B  = 128 * 64;        // 8192 B per tile array
static constexpr int STAGE_B = 4 * TILE_B;      // Ah,Al,Bh,Bl = 32768 B
static constexpr int NSTAGE  = 3;
static constexpr int SMEM_DYN = NSTAGE * STAGE_B;  // 98304 B

static constexpr int CTX_STAGE_B = 3 * TILE_B;     // A,Bh,Bl = 24576 B
static constexpr int CTX_SMEM    = NSTAGE * CTX_STAGE_B;  // 73728 B

__device__ __forceinline__ uint32_t sw_addr(int row, int chunk) {
    return (uint32_t)(row * 64 + ((chunk ^ ((row >> 1) & 3)) << 4));
}

// ---------------------------------------------------------------------------
// bf16x3 GEMM (emulated fp32) on mma.sync:  C[M,N] = A[M,K] * B[N,K]^T
// Tile 128x128, BK=32, 128 thr (4 warps, 2Mx2N, warp tile 64x64)
// 3-stage cp.async pipeline, one __syncthreads per K-iteration.
// ---------------------------------------------------------------------------
__global__ __launch_bounds__(128, 2)
void gemm_bf16x3(const __nv_bfloat16* __restrict__ Ah, const __nv_bfloat16* __restrict__ Al,
                 const __nv_bfloat16* __restrict__ Bh, const __nv_bfloat16* __restrict__ Bl,
                 float* __restrict__ Cf,
                 __nv_bfloat16* __restrict__ Chi, __nv_bfloat16* __restrict__ Clo,
                 const float* __restrict__ bias,
                 int K, int ldC,
                 long long sA, long long sB, long long sC)
{
    extern __shared__ __align__(128) char sm[];
    const uint32_t s0 = smem_u32(sm);

    const int tid  = threadIdx.x;
    const int wid  = tid >> 5;
    const int lane = tid & 31;
    const int wm   = wid & 1;
    const int wn   = wid >> 1;

    const long long zA = (long long)blockIdx.z * sA;
    const long long zB = (long long)blockIdx.z * sB;
    const __nv_bfloat16* pAh = Ah + zA + (long long)(blockIdx.y * 128) * K;
    const __nv_bfloat16* pAl = Al + zA + (long long)(blockIdx.y * 128) * K;
    const __nv_bfloat16* pBh = Bh + zB + (long long)(blockIdx.x * 128) * K;
    const __nv_bfloat16* pBl = Bl + zB + (long long)(blockIdx.x * 128) * K;

    const int lr0 = tid >> 2;
    const int lc  = tid & 3;
    auto tileLoad = [&](int stage, int k0) {
        const uint32_t db = s0 + stage * STAGE_B;
#pragma unroll
        for (int i = 0; i < 4; ++i) {
            const int r = lr0 + i * 32;
            const uint32_t so = sw_addr(r, lc);
            const long long go = (long long)r * K + k0 + lc * 8;
            cp_async16(db + 0 * TILE_B + so, pAh + go);
            cp_async16(db + 1 * TILE_B + so, pAl + go);
            cp_async16(db + 2 * TILE_B + so, pBh + go);
            cp_async16(db + 3 * TILE_B + so, pBl + go);
        }
        CP_COMMIT();
    };

    const int rowA0 = wm * 64 + (lane & 15);
    const int hiA   = lane >> 4;
    const int rowB0 = wn * 64 + (lane & 7) + ((lane & 16) >> 1);
    const int hiB   = (lane & 8) >> 3;

    float acc[4][8][4];
#pragma unroll
    for (int a = 0; a < 4; ++a)
#pragma unroll
        for (int b = 0; b < 8; ++b)
#pragma unroll
            for (int c = 0; c < 4; ++c) acc[a][b][c] = 0.0f;

    const int nk = K >> 5;
    tileLoad(0, 0);
    tileLoad(1, 32);

    int stage = 0;
    for (int it = 0; it < nk; ++it) {
        if (it + 2 < nk) { CP_WAIT1(); } else { CP_WAIT0(); }
        __syncthreads();
        if (it + 2 < nk) {
            int ns = stage + 2; if (ns >= NSTAGE) ns -= NSTAGE;
            tileLoad(ns, (it + 2) << 5);
        }

        const uint32_t sb = s0 + stage * STAGE_B;
#pragma unroll
        for (int ks = 0; ks < 2; ++ks) {
            uint32_t fAh[4][4], fAl[4][4];
#pragma unroll
            for (int mt = 0; mt < 4; ++mt) {
                const int r = rowA0 + mt * 16;
                const uint32_t ao = sw_addr(r, hiA + ks * 2);
                ldm_x4(fAh[mt], sb + 0 * TILE_B + ao);
                ldm_x4(fAl[mt], sb + 1 * TILE_B + ao);
            }
#pragma unroll
            for (int pp = 0; pp < 4; ++pp) {
                const int rb = rowB0 + pp * 16;
                const uint32_t bo = sw_addr(rb, hiB + ks * 2);
                uint32_t fBh[4], fBl[4];
                ldm_x4(fBh, sb + 2 * TILE_B + bo);
                ldm_x4(fBl, sb + 3 * TILE_B + bo);
#pragma unroll
                for (int q = 0; q < 2; ++q) {
                    const int nt = pp * 2 + q;
#pragma unroll
                    for (int mt = 0; mt < 4; ++mt)
                        mma_bf16(acc[mt][nt], fAh[mt], fBh + q * 2);
#pragma unroll
                    for (int mt = 0; mt < 4; ++mt)
                        mma_bf16(acc[mt][nt], fAh[mt], fBl + q * 2);
#pragma unroll
                    for (int mt = 0; mt < 4; ++mt)
                        mma_bf16(acc[mt][nt], fAl[mt], fBh + q * 2);
                }
            }
        }
        if (++stage >= NSTAGE) stage = 0;
    }

    // ---------------- epilogue ----------------
    const int rBase = blockIdx.y * 128 + wm * 64 + (lane >> 2);
    const int cBase = blockIdx.x * 128 + wn * 64 + (lane & 3) * 2;
    const long long zC = (long long)blockIdx.z * sC;

#pragma unroll
    for (int mt = 0; mt < 4; ++mt) {
#pragma unroll
        for (int h = 0; h < 2; ++h) {
            const int row = rBase + mt * 16 + h * 8;
#pragma unroll
            for (int nt = 0; nt < 8; ++nt) {
                const int col = cBase + nt * 8;
                float v0 = acc[mt][nt][h * 2 + 0];
                float v1 = acc[mt][nt][h * 2 + 1];
                if (bias) { v0 += bias[col]; v1 += bias[col + 1]; }
                const long long o = zC + (long long)row * ldC + col;
                if (Cf) {
                    float2 fv; fv.x = v0; fv.y = v1;
                    *(float2*)(Cf + o) = fv;
                }
                if (Chi) {
                    __nv_bfloat16 h0, l0, h1, l1;
                    split2(v0, h0, l0); split2(v1, h1, l1);
                    __nv_bfloat162 hv; hv.x = h0; hv.y = h1;
                    __nv_bfloat162 lv; lv.x = l0; lv.y = l1;
                    *(__nv_bfloat162*)(Chi + o) = hv;
                    *(__nv_bfloat162*)(Clo + o) = lv;
                }
            }
        }
    }
}

// ---------------------------------------------------------------------------
// fp16 2-term GEMM for context: C[M,N] = A[M,K] * B[N,K]^T
// A single fp16 (alignment, linear sensitivity), B fp16 hi/lo.
// Same tiling/pipeline as gemm_bf16x3, 2 MMA terms.
// ---------------------------------------------------------------------------
__global__ __launch_bounds__(128, 2)
void gemm_ctx_fp16(const __half* __restrict__ A,
                   const __half* __restrict__ Bh, const __half* __restrict__ Bl,
                   float* __restrict__ Cf,
                   int K, int ldC,
                   long long sA, long long sB, long long sC)
{
    extern __shared__ __align__(128) char sm[];
    const uint32_t s0 = smem_u32(sm);

    const int tid  = threadIdx.x;
    const int wid  = tid >> 5;
    const int lane = tid & 31;
    const int wm   = wid & 1;
    const int wn   = wid >> 1;

    const long long zA = (long long)blockIdx.z * sA;
    const long long zB = (long long)blockIdx.z * sB;
    const __half* pA  = A  + zA + (long long)(blockIdx.y * 128) * K;
    const __half* pBh = Bh + zB + (long long)(blockIdx.x * 128) * K;
    const __half* pBl = Bl + zB + (long long)(blockIdx.x * 128) * K;

    const int lr0 = tid >> 2;
    const int lc  = tid & 3;
    auto tileLoad = [&](int stage, int k0) {
        const uint32_t db = s0 + stage * CTX_STAGE_B;
#pragma unroll
        for (int i = 0; i < 4; ++i) {
            const int r = lr0 + i * 32;
            const uint32_t so = sw_addr(r, lc);
            const long long go = (long long)r * K + k0 + lc * 8;
            cp_async16(db + 0 * TILE_B + so, pA  + go);
            cp_async16(db + 1 * TILE_B + so, pBh + go);
            cp_async16(db + 2 * TILE_B + so, pBl + go);
        }
        CP_COMMIT();
    };

    const int rowA0 = wm * 64 + (lane & 15);
    const int hiA   = lane >> 4;
    const int rowB0 = wn * 64 + (lane & 7) + ((lane & 16) >> 1);
    const int hiB   = (lane & 8) >> 3;

    float acc[4][8][4];
#pragma unroll
    for (int a = 0; a < 4; ++a)
#pragma unroll
        for (int b = 0; b < 8; ++b)
#pragma unroll
            for (int c = 0; c < 4; ++c) acc[a][b][c] = 0.0f;

    const int nk = K >> 5;
    tileLoad(0, 0);
    tileLoad(1, 32);

    int stage = 0;
    for (int it = 0; it < nk; ++it) {
        if (it + 2 < nk) { CP_WAIT1(); } else { CP_WAIT0(); }
        __syncthreads();
        if (it + 2 < nk) {
            int ns = stage + 2; if (ns >= NSTAGE) ns -= NSTAGE;
            tileLoad(ns, (it + 2) << 5);
        }

        const uint32_t sb = s0 + stage * CTX_STAGE_B;
#pragma unroll
        for (int ks = 0; ks < 2; ++ks) {
            uint32_t fA[4][4];
#pragma unroll
            for (int mt = 0; mt < 4; ++mt) {
                const int r = rowA0 + mt * 16;
                const uint32_t ao = sw_addr(r, hiA + ks * 2);
                ldm_x4(fA[mt], sb + 0 * TILE_B + ao);
            }
#pragma unroll
            for (int pp = 0; pp < 4; ++pp) {
                const int rb = rowB0 + pp * 16;
                const uint32_t bo = sw_addr(rb, hiB + ks * 2);
                uint32_t fBh[4], fBl[4];
                ldm_x4(fBh, sb + 1 * TILE_B + bo);
                ldm_x4(fBl, sb + 2 * TILE_B + bo);
#pragma unroll
                for (int q = 0; q < 2; ++q) {
                    const int nt = pp * 2 + q;
#pragma unroll
                    for (int mt = 0; mt < 4; ++mt)
                        mma_fp16(acc[mt][nt], fA[mt], fBh + q * 2);
#pragma unroll
                    for (int mt = 0; mt < 4; ++mt)
                        mma_fp16(acc[mt][nt], fA[mt], fBl + q * 2);
                }
            }
        }
        if (++stage >= NSTAGE) stage = 0;
    }

    // ---------------- epilogue ----------------
    const int rBase = blockIdx.y * 128 + wm * 64 + (lane >> 2);
    const int cBase = blockIdx.x * 128 + wn * 64 + (lane & 3) * 2;
    const long long zC = (long long)blockIdx.z * sC;

#pragma unroll
    for (int mt = 0; mt < 4; ++mt) {
#pragma unroll
        for (int h = 0; h < 2; ++h) {
            const int row = rBase + mt * 16 + h * 8;
#pragma unroll
            for (int nt = 0; nt < 8; ++nt) {
                const int col = cBase + nt * 8;
                float2 fv;
                fv.x = acc[mt][nt][h * 2 + 0];
                fv.y = acc[mt][nt][h * 2 + 1];
                *(float2*)(Cf + zC + (long long)row * ldC + col) = fv;
            }
        }
    }
}

// ---------------------------------------------------------------------------
// Elementwise fp32 -> (hi, lo) bf16 split
// ---------------------------------------------------------------------------
__global__ __launch_bounds__(256)
void convert_split(const float4* __restrict__ in, __nv_bfloat16* __restrict__ oh,
                   __nv_bfloat16* __restrict__ ol, int n4)
{
    __nv_bfloat162* oh2 = reinterpret_cast<__nv_bfloat162*>(oh);
    __nv_bfloat162* ol2 = reinterpret_cast<__nv_bfloat162*>(ol);
    for (int i = blockIdx.x * 256 + threadIdx.x; i < n4; i += gridDim.x * 256) {
        float4 v = in[i];
        __nv_bfloat16 h0, l0, h1, l1, h2, l2, h3, l3;
        split2(v.x, h0, l0); split2(v.y, h1, l1);
        split2(v.z, h2, l2); split2(v.w, h3, l3);
        __nv_bfloat162 a; a.x = h0; a.y = h1;
        __nv_bfloat162 b; b.x = h2; b.y = h3;
        oh2[i * 2] = a; oh2[i * 2 + 1] = b;
        a.x = l0; a.y = l1; b.x = l2; b.y = l3;
        ol2[i * 2] = a; ol2[i * 2 + 1] = b;
    }
}

// ---------------------------------------------------------------------------
// Fused enc prep: read enc once per batch; write row-major bf16 hi/lo AND
// transposed [D][TK] fp16 hi/lo (for the fp16 context GEMM).
// blockDim (32,8), grid (D/32, TK/32, B)
// ---------------------------------------------------------------------------
__global__ __launch_bounds__(256)
void prep_enc(const float* __restrict__ in,
              __nv_bfloat16* __restrict__ rh, __nv_bfloat16* __restrict__ rl,
              __half* __restrict__ th, __half* __restrict__ tl)
{
    __shared__ float t[32][33];
    const long long zi = (long long)blockIdx.z * TK * D;
    const long long zo = (long long)blockIdx.z * D * TK;
    const int c0 = blockIdx.x * 32, r0 = blockIdx.y * 32;
    const int tx = threadIdx.x, ty0 = threadIdx.y;
#pragma unroll
    for (int i = 0; i < 4; ++i) {
        int ty = ty0 + i * 8;
        float v = in[zi + (long long)(r0 + ty) * D + c0 + tx];
        t[ty][tx] = v;
        __nv_bfloat16 h, l; split2(v, h, l);
        long long o = zi + (long long)(r0 + ty) * D + c0 + tx;
        rh[o] = h; rl[o] = l;
    }
    __syncthreads();
#pragma unroll
    for (int i = 0; i < 4; ++i) {
        int ty = ty0 + i * 8;
        float v = t[tx][ty];                 // = in[r0+tx][c0+ty]
        __half h, l; split2h(v, h, l);
        long long o = zo + (long long)(c0 + ty) * TK + r0 + tx;
        th[o] = h; tl[o] = l;
    }
}

// ---------------------------------------------------------------------------
// Transpose + split (for W): in [R][C] fp32 -> out [C][R] bf16 hi/lo
// ---------------------------------------------------------------------------
__global__ __launch_bounds__(256)
void transpose_split(const float* __restrict__ in, __nv_bfloat16* __restrict__ oh,
                     __nv_bfloat16* __restrict__ ol, int R, int C)
{
    __shared__ float t[32][33];
    const int c0 = blockIdx.x * 32, r0 = blockIdx.y * 32;
    const int tx = threadIdx.x, ty0 = threadIdx.y;
#pragma unroll
    for (int i = 0; i < 4; ++i) {
        int ty = ty0 + i * 8;
        t[ty][tx] = in[(long long)(r0 + ty) * C + c0 + tx];
    }
    __syncthreads();
#pragma unroll
    for (int i = 0; i < 4; ++i) {
        int ty = ty0 + i * 8;
        float v = t[tx][ty];
        __nv_bfloat16 h, l; split2(v, h, l);
        long long o = (long long)(c0 + ty) * R + r0 + tx;
        oh[o] = h; ol[o] = l;
    }
}

// ---------------------------------------------------------------------------
// In-place row softmax over 2048 cols + single fp16 output for context GEMM
// ---------------------------------------------------------------------------
__global__ __launch_bounds__(256)
void softmax2048(float* __restrict__ data, __half* __restrict__ alh)
{
    float* row = data + (long long)blockIdx.x * 2048;
    __half2* hrow = reinterpret_cast<__half2*>(alh + (long long)blockIdx.x * 2048);
    const int tid = threadIdx.x;

    float4 v0 = reinterpret_cast<float4*>(row)[tid];
    float4 v1 = reinterpret_cast<float4*>(row)[tid + 256];

    __shared__ float smr[8];
    __shared__ float bcast;

    float m = fmaxf(fmaxf(fmaxf(v0.x, v0.y), fmaxf(v0.z, v0.w)),
                    fmaxf(fmaxf(v1.x, v1.y), fmaxf(v1.z, v1.w)));
#pragma unroll
    for (int o = 16; o > 0; o >>= 1) m = fmaxf(m, __shfl_xor_sync(0xffffffffu, m, o));
    if ((tid & 31) == 0) smr[tid >> 5] = m;
    __syncthreads();
    if (tid == 0) {
        float t = smr[0];
#pragma unroll
        for (int i = 1; i < 8; ++i) t = fmaxf(t, smr[i]);
        bcast = t;
    }
    __syncthreads();
    m = bcast;
    __syncthreads();

    v0.x = __expf(v0.x - m); v0.y = __expf(v0.y - m);
    v0.z = __expf(v0.z - m); v0.w = __expf(v0.w - m);
    v1.x = __expf(v1.x - m); v1.y = __expf(v1.y - m);
    v1.z = __expf(v1.z - m); v1.w = __expf(v1.w - m);
    float s = (v0.x + v0.y) + (v0.z + v0.w) + (v1.x + v1.y) + (v1.z + v1.w);
#pragma unroll
    for (int o = 16; o > 0; o >>= 1) s += __shfl_xor_sync(0xffffffffu, s, o);
    if ((tid & 31) == 0) smr[tid >> 5] = s;
    __syncthreads();
    if (tid == 0) {
        float t = 0.0f;
#pragma unroll
        for (int i = 0; i < 8; ++i) t += smr[i];
        bcast = 1.0f / t;
    }
    __syncthreads();
    const float r = bcast;

    v0.x *= r; v0.y *= r; v0.z *= r; v0.w *= r;
    v1.x *= r; v1.y *= r; v1.z *= r; v1.w *= r;
    reinterpret_cast<float4*>(row)[tid]       = v0;
    reinterpret_cast<float4*>(row)[tid + 256] = v1;

    hrow[tid * 2]             = __floats2half2_rn(v0.x, v0.y);
    hrow[tid * 2 + 1]         = __floats2half2_rn(v0.z, v0.w);
    hrow[(256 + tid) * 2]     = __floats2half2_rn(v1.x, v1.y);
    hrow[(256 + tid) * 2 + 1] = __floats2half2_rn(v1.z, v1.w);
}

// ---------------------------------------------------------------------------
extern "C" void kernel_launch(void* const* d_in, const int* in_sizes, int n_in,
                              void* d_out, int out_size)
{
    const float* dec = (const float*)d_in[0];   // [B, TQ, D]
    const float* enc = (const float*)d_in[1];   // [B, TK, D]
    const float* Wk  = (const float*)d_in[2];   // [D, D]
    const float* bia = (const float*)d_in[3];   // [D]
    if (n_in >= 4 && in_sizes[2] == D && in_sizes[3] == D * D) {
        const float* t = Wk; Wk = bia; bia = t;
    }
    // NOTE: bias adds dec[q]·b (constant per row q) to every score column ->
    // softmax is shift-invariant -> bias cannot affect either output. Still
    // passed to the keys GEMM for exactness (it's zeros in the reference).

    float* out     = (float*)d_out;
    float* context = out;                          // B*TQ*D
    float* align   = out + (size_t)Bsz * TQ * D;   // B*TQ*TK (score scratch too)

    __nv_bfloat16 *dec_h, *dec_l, *enc_h, *enc_l;
    __half *encT_h, *encT_l, *al_f16;
    __nv_bfloat16 *Wt_h, *Wt_l, *key_h, *key_l;
    cudaGetSymbolAddress((void**)&dec_h,  g_dec_h);
    cudaGetSymbolAddress((void**)&dec_l,  g_dec_l);
    cudaGetSymbolAddress((void**)&enc_h,  g_enc_h);
    cudaGetSymbolAddress((void**)&enc_l,  g_enc_l);
    cudaGetSymbolAddress((void**)&encT_h, g_encT_h);
    cudaGetSymbolAddress((void**)&encT_l, g_encT_l);
    cudaGetSymbolAddress((void**)&Wt_h,   g_Wt_h);
    cudaGetSymbolAddress((void**)&Wt_l,   g_Wt_l);
    cudaGetSymbolAddress((void**)&key_h,  g_key_h);
    cudaGetSymbolAddress((void**)&key_l,  g_key_l);
    cudaGetSymbolAddress((void**)&al_f16, g_al_f16);

    cudaFuncSetAttribute(gemm_bf16x3,  cudaFuncAttributeMaxDynamicSharedMemorySize, SMEM_DYN);
    cudaFuncSetAttribute(gemm_ctx_fp16, cudaFuncAttributeMaxDynamicSharedMemorySize, CTX_SMEM);

    // 1) prep
    const int n4 = Bsz * TQ * D / 4;
    convert_split<<<4096, 256>>>((const float4*)dec, dec_h, dec_l, n4);
    prep_enc<<<dim3(D / 32, TK / 32, Bsz), dim3(32, 8)>>>(
        enc, enc_h, enc_l, encT_h, encT_l);
    transpose_split<<<dim3(D / 32, D / 32, 1), dim3(32, 8)>>>(
        Wk, Wt_h, Wt_l, D, D);

    // 2) keys = enc @ W + bias -> split bf16   (M=32768, N=1024, K=1024)
    gemm_bf16x3<<<dim3(D / 128, (Bsz * TK) / 128, 1), 128, SMEM_DYN>>>(
        enc_h, enc_l, Wt_h, Wt_l,
        nullptr, key_h, key_l, bia,
        D, D, 0LL, 0LL, 0LL);

    // 3) score[b] = dec[b] @ keys[b]^T -> fp32 into align region
    gemm_bf16x3<<<dim3(TK / 128, TQ / 128, Bsz), 128, SMEM_DYN>>>(
        dec_h, dec_l, key_h, key_l,
        align, nullptr, nullptr, nullptr,
        D, TK, (long long)TQ * D, (long long)TK * D, (long long)TQ * TK);

    // 4) softmax (in place) + fp16 alignment for context GEMM
    softmax2048<<<Bsz * TQ, 256>>>(align, al_f16);

    // 5) context[b] = align[b] @ enc[b]   (fp16 2-term, B = encT fp16 hi/lo)
    gemm_ctx_fp16<<<dim3(D / 128, TQ / 128, Bsz), 128, CTX_SMEM>>>(
        al_f16, encT_h, encT_l,
        context, TK, D,
        (long long)TQ * TK, (long long)D * TK, (long long)TQ * D);
}

// round 8
// speedup vs baseline: 3.8496x; 1.0037x over previous
#include <cuda_runtime.h>
#include <cuda_bf16.h>
#include <cuda_fp16.h>
#include <cstdint>

// LuongAttention B=16, TQ=2048, TK=2048, D=1024
// out = [context (B*TQ*D fp32) | alignment (B*TQ*TK fp32)]
static constexpr int Bsz = 16;
static constexpr int TQ  = 2048;
static constexpr int TK  = 2048;
static constexpr int D   = 1024;

// ---------------- device scratch (allocation-free, 16B aligned) ----------------
__device__ __align__(16) __nv_bfloat16 g_dec_h[(size_t)Bsz * TQ * D];
__device__ __align__(16) __nv_bfloat16 g_dec_l[(size_t)Bsz * TQ * D];
__device__ __align__(16) __nv_bfloat16 g_enc_h[(size_t)Bsz * TK * D];
__device__ __align__(16) __nv_bfloat16 g_enc_l[(size_t)Bsz * TK * D];
__device__ __align__(16) __half        g_encT_h[(size_t)Bsz * D * TK];   // fp16 hi
__device__ __align__(16) __half        g_encT_l[(size_t)Bsz * D * TK];   // fp16 lo
__device__ __align__(16) __nv_bfloat16 g_Wt_h[(size_t)D * D];
__device__ __align__(16) __nv_bfloat16 g_Wt_l[(size_t)D * D];
__device__ __align__(16) __nv_bfloat16 g_key_h[(size_t)Bsz * TK * D];
__device__ __align__(16) __nv_bfloat16 g_key_l[(size_t)Bsz * TK * D];
__device__ __align__(16) __half        g_al_f16[(size_t)Bsz * TQ * TK];  // fp16 alignment

// ---------------- helpers ----------------
__device__ __forceinline__ uint32_t smem_u32(const void* p) {
    uint32_t a;
    asm("{ .reg .u64 t; cvta.to.shared.u64 t, %1; cvt.u32.u64 %0, t; }"
        : "=r"(a) : "l"(p));
    return a;
}
__device__ __forceinline__ void cp_async16(uint32_t dst, const void* src) {
    asm volatile("{ .reg .u64 g; cvta.to.global.u64 g, %1;"
                 "  cp.async.cg.shared.global [%0], [g], 16; }"
                 :: "r"(dst), "l"(src) : "memory");
}
#define CP_COMMIT() asm volatile("cp.async.commit_group;" ::: "memory")
#define CP_WAIT1()  asm volatile("cp.async.wait_group 1;" ::: "memory")
#define CP_WAIT0()  asm volatile("cp.async.wait_group 0;" ::: "memory")

__device__ __forceinline__ void ldm_x4(uint32_t* r, uint32_t addr) {
    asm volatile("ldmatrix.sync.aligned.m8n8.x4.shared.b16 {%0,%1,%2,%3}, [%4];"
                 : "=r"(r[0]), "=r"(r[1]), "=r"(r[2]), "=r"(r[3]) : "r"(addr));
}
__device__ __forceinline__ void mma_bf16(float* c, const uint32_t* a, const uint32_t* b) {
    asm volatile("mma.sync.aligned.m16n8k16.row.col.f32.bf16.bf16.f32 "
                 "{%0,%1,%2,%3}, {%4,%5,%6,%7}, {%8,%9}, {%0,%1,%2,%3};"
                 : "+f"(c[0]), "+f"(c[1]), "+f"(c[2]), "+f"(c[3])
                 : "r"(a[0]), "r"(a[1]), "r"(a[2]), "r"(a[3]), "r"(b[0]), "r"(b[1]));
}
__device__ __forceinline__ void mma_fp16(float* c, const uint32_t* a, const uint32_t* b) {
    asm volatile("mma.sync.aligned.m16n8k16.row.col.f32.f16.f16.f32 "
                 "{%0,%1,%2,%3}, {%4,%5,%6,%7}, {%8,%9}, {%0,%1,%2,%3};"
                 : "+f"(c[0]), "+f"(c[1]), "+f"(c[2]), "+f"(c[3])
                 : "r"(a[0]), "r"(a[1]), "r"(a[2]), "r"(a[3]), "r"(b[0]), "r"(b[1]));
}
__device__ __forceinline__ void split2(float x, __nv_bfloat16& h, __nv_bfloat16& l) {
    h = __float2bfloat16_rn(x);
    l = __float2bfloat16_rn(x - __bfloat162float(h));
}
__device__ __forceinline__ void split2h(float x, __half& h, __half& l) {
    h = __float2half_rn(x);
    l = __float2half_rn(x - __half2float(h));
}

// smem geometry: 128 rows x 64B (32 elems), XOR swizzle -> no padding
static constexpr int TILE_B  = 128 * 64;        // 8192 B per tile array
static constexpr int STAGE_B = 4 * TILE_B;      // Ah,Al,Bh,Bl = 32768 B
static constexpr int NSTAGE  = 3;
static constexpr int SMEM_DYN = NSTAGE * STAGE_B;  // 98304 B

static constexpr int CTX_STAGE_B = 3 * TILE_B;     // A,Bh,Bl = 24576 B
static constexpr int CTX_SMEM    = NSTAGE * CTX_STAGE_B;  // 73728 B

__device__ __forceinline__ uint32_t sw_addr(int row, int chunk) {
    return (uint32_t)(row * 64 + ((chunk ^ ((row >> 1) & 3)) << 4));
}

// ---------------------------------------------------------------------------
// bf16x3 GEMM (emulated fp32) on mma.sync:  C[M,N] = A[M,K] * B[N,K]^T
// Tile 128x128, BK=32, 128 thr (4 warps, 2Mx2N, warp tile 64x64)
// 3-stage cp.async pipeline, one __syncthreads per K-iteration.
// Fragment-upfront schedule: all 16 LDSM per ks-step issue before the 96 MMAs.
// ---------------------------------------------------------------------------
__global__ __launch_bounds__(128, 2)
void gemm_bf16x3(const __nv_bfloat16* __restrict__ Ah, const __nv_bfloat16* __restrict__ Al,
                 const __nv_bfloat16* __restrict__ Bh, const __nv_bfloat16* __restrict__ Bl,
                 float* __restrict__ Cf,
                 __nv_bfloat16* __restrict__ Chi, __nv_bfloat16* __restrict__ Clo,
                 const float* __restrict__ bias,
                 int K, int ldC,
                 long long sA, long long sB, long long sC)
{
    extern __shared__ __align__(128) char sm[];
    const uint32_t s0 = smem_u32(sm);

    const int tid  = threadIdx.x;
    const int wid  = tid >> 5;
    const int lane = tid & 31;
    const int wm   = wid & 1;
    const int wn   = wid >> 1;

    const long long zA = (long long)blockIdx.z * sA;
    const long long zB = (long long)blockIdx.z * sB;
    const __nv_bfloat16* pAh = Ah + zA + (long long)(blockIdx.y * 128) * K;
    const __nv_bfloat16* pAl = Al + zA + (long long)(blockIdx.y * 128) * K;
    const __nv_bfloat16* pBh = Bh + zB + (long long)(blockIdx.x * 128) * K;
    const __nv_bfloat16* pBl = Bl + zB + (long long)(blockIdx.x * 128) * K;

    const int lr0 = tid >> 2;
    const int lc  = tid & 3;
    auto tileLoad = [&](int stage, int k0) {
        const uint32_t db = s0 + stage * STAGE_B;
#pragma unroll
        for (int i = 0; i < 4; ++i) {
            const int r = lr0 + i * 32;
            const uint32_t so = sw_addr(r, lc);
            const long long go = (long long)r * K + k0 + lc * 8;
            cp_async16(db + 0 * TILE_B + so, pAh + go);
            cp_async16(db + 1 * TILE_B + so, pAl + go);
            cp_async16(db + 2 * TILE_B + so, pBh + go);
            cp_async16(db + 3 * TILE_B + so, pBl + go);
        }
        CP_COMMIT();
    };

    const int rowA0 = wm * 64 + (lane & 15);
    const int hiA   = lane >> 4;
    const int rowB0 = wn * 64 + (lane & 7) + ((lane & 16) >> 1);
    const int hiB   = (lane & 8) >> 3;

    float acc[4][8][4];
#pragma unroll
    for (int a = 0; a < 4; ++a)
#pragma unroll
        for (int b = 0; b < 8; ++b)
#pragma unroll
            for (int c = 0; c < 4; ++c) acc[a][b][c] = 0.0f;

    const int nk = K >> 5;
    tileLoad(0, 0);
    tileLoad(1, 32);

    int stage = 0;
    for (int it = 0; it < nk; ++it) {
        if (it + 2 < nk) { CP_WAIT1(); } else { CP_WAIT0(); }
        __syncthreads();
        if (it + 2 < nk) {
            int ns = stage + 2; if (ns >= NSTAGE) ns -= NSTAGE;
            tileLoad(ns, (it + 2) << 5);
        }

        const uint32_t sb = s0 + stage * STAGE_B;
#pragma unroll
        for (int ks = 0; ks < 2; ++ks) {
            // ---- all fragments for this ks-step up front (16 LDSM.x4) ----
            uint32_t fAh[4][4], fAl[4][4], fBh[4][4], fBl[4][4];
#pragma unroll
            for (int mt = 0; mt < 4; ++mt) {
                const int r = rowA0 + mt * 16;
                const uint32_t ao = sw_addr(r, hiA + ks * 2);
                ldm_x4(fAh[mt], sb + 0 * TILE_B + ao);
                ldm_x4(fAl[mt], sb + 1 * TILE_B + ao);
            }
#pragma unroll
            for (int pp = 0; pp < 4; ++pp) {
                const int rb = rowB0 + pp * 16;
                const uint32_t bo = sw_addr(rb, hiB + ks * 2);
                ldm_x4(fBh[pp], sb + 2 * TILE_B + bo);
                ldm_x4(fBl[pp], sb + 3 * TILE_B + bo);
            }
            // ---- 96 MMAs, term-major (dep distance 4 accumulators) ----
#pragma unroll
            for (int pp = 0; pp < 4; ++pp) {
#pragma unroll
                for (int q = 0; q < 2; ++q) {
                    const int nt = pp * 2 + q;
#pragma unroll
                    for (int mt = 0; mt < 4; ++mt)
                        mma_bf16(acc[mt][nt], fAh[mt], fBh[pp] + q * 2);
#pragma unroll
                    for (int mt = 0; mt < 4; ++mt)
                        mma_bf16(acc[mt][nt], fAh[mt], fBl[pp] + q * 2);
#pragma unroll
                    for (int mt = 0; mt < 4; ++mt)
                        mma_bf16(acc[mt][nt], fAl[mt], fBh[pp] + q * 2);
                }
            }
        }
        if (++stage >= NSTAGE) stage = 0;
    }

    // ---------------- epilogue ----------------
    const int rBase = blockIdx.y * 128 + wm * 64 + (lane >> 2);
    const int cBase = blockIdx.x * 128 + wn * 64 + (lane & 3) * 2;
    const long long zC = (long long)blockIdx.z * sC;

#pragma unroll
    for (int mt = 0; mt < 4; ++mt) {
#pragma unroll
        for (int h = 0; h < 2; ++h) {
            const int row = rBase + mt * 16 + h * 8;
#pragma unroll
            for (int nt = 0; nt < 8; ++nt) {
                const int col = cBase + nt * 8;
                float v0 = acc[mt][nt][h * 2 + 0];
                float v1 = acc[mt][nt][h * 2 + 1];
                if (bias) { v0 += bias[col]; v1 += bias[col + 1]; }
                const long long o = zC + (long long)row * ldC + col;
                if (Cf) {
                    float2 fv; fv.x = v0; fv.y = v1;
                    *(float2*)(Cf + o) = fv;
                }
                if (Chi) {
                    __nv_bfloat16 h0, l0, h1, l1;
                    split2(v0, h0, l0); split2(v1, h1, l1);
                    __nv_bfloat162 hv; hv.x = h0; hv.y = h1;
                    __nv_bfloat162 lv; lv.x = l0; lv.y = l1;
                    *(__nv_bfloat162*)(Chi + o) = hv;
                    *(__nv_bfloat162*)(Clo + o) = lv;
                }
            }
        }
    }
}

// ---------------------------------------------------------------------------
// fp16 2-term GEMM for context: C[M,N] = A[M,K] * B[N,K]^T
// A single fp16 (alignment), B fp16 hi/lo. Fragment-upfront schedule.
// ---------------------------------------------------------------------------
__global__ __launch_bounds__(128, 2)
void gemm_ctx_fp16(const __half* __restrict__ A,
                   const __half* __restrict__ Bh, const __half* __restrict__ Bl,
                   float* __restrict__ Cf,
                   int K, int ldC,
                   long long sA, long long sB, long long sC)
{
    extern __shared__ __align__(128) char sm[];
    const uint32_t s0 = smem_u32(sm);

    const int tid  = threadIdx.x;
    const int wid  = tid >> 5;
    const int lane = tid & 31;
    const int wm   = wid & 1;
    const int wn   = wid >> 1;

    const long long zA = (long long)blockIdx.z * sA;
    const long long zB = (long long)blockIdx.z * sB;
    const __half* pA  = A  + zA + (long long)(blockIdx.y * 128) * K;
    const __half* pBh = Bh + zB + (long long)(blockIdx.x * 128) * K;
    const __half* pBl = Bl + zB + (long long)(blockIdx.x * 128) * K;

    const int lr0 = tid >> 2;
    const int lc  = tid & 3;
    auto tileLoad = [&](int stage, int k0) {
        const uint32_t db = s0 + stage * CTX_STAGE_B;
#pragma unroll
        for (int i = 0; i < 4; ++i) {
            const int r = lr0 + i * 32;
            const uint32_t so = sw_addr(r, lc);
            const long long go = (long long)r * K + k0 + lc * 8;
            cp_async16(db + 0 * TILE_B + so, pA  + go);
            cp_async16(db + 1 * TILE_B + so, pBh + go);
            cp_async16(db + 2 * TILE_B + so, pBl + go);
        }
        CP_COMMIT();
    };

    const int rowA0 = wm * 64 + (lane & 15);
    const int hiA   = lane >> 4;
    const int rowB0 = wn * 64 + (lane & 7) + ((lane & 16) >> 1);
    const int hiB   = (lane & 8) >> 3;

    float acc[4][8][4];
#pragma unroll
    for (int a = 0; a < 4; ++a)
#pragma unroll
        for (int b = 0; b < 8; ++b)
#pragma unroll
            for (int c = 0; c < 4; ++c) acc[a][b][c] = 0.0f;

    const int nk = K >> 5;
    tileLoad(0, 0);
    tileLoad(1, 32);

    int stage = 0;
    for (int it = 0; it < nk; ++it) {
        if (it + 2 < nk) { CP_WAIT1(); } else { CP_WAIT0(); }
        __syncthreads();
        if (it + 2 < nk) {
            int ns = stage + 2; if (ns >= NSTAGE) ns -= NSTAGE;
            tileLoad(ns, (it + 2) << 5);
        }

        const uint32_t sb = s0 + stage * CTX_STAGE_B;
#pragma unroll
        for (int ks = 0; ks < 2; ++ks) {
            uint32_t fA[4][4], fBh[4][4], fBl[4][4];
#pragma unroll
            for (int mt = 0; mt < 4; ++mt) {
                const int r = rowA0 + mt * 16;
                const uint32_t ao = sw_addr(r, hiA + ks * 2);
                ldm_x4(fA[mt], sb + 0 * TILE_B + ao);
            }
#pragma unroll
            for (int pp = 0; pp < 4; ++pp) {
                const int rb = rowB0 + pp * 16;
                const uint32_t bo = sw_addr(rb, hiB + ks * 2);
                ldm_x4(fBh[pp], sb + 1 * TILE_B + bo);
                ldm_x4(fBl[pp], sb + 2 * TILE_B + bo);
            }
#pragma unroll
            for (int pp = 0; pp < 4; ++pp) {
#pragma unroll
                for (int q = 0; q < 2; ++q) {
                    const int nt = pp * 2 + q;
#pragma unroll
                    for (int mt = 0; mt < 4; ++mt)
                        mma_fp16(acc[mt][nt], fA[mt], fBh[pp] + q * 2);
#pragma unroll
                    for (int mt = 0; mt < 4; ++mt)
                        mma_fp16(acc[mt][nt], fA[mt], fBl[pp] + q * 2);
                }
            }
        }
        if (++stage >= NSTAGE) stage = 0;
    }

    // ---------------- epilogue ----------------
    const int rBase = blockIdx.y * 128 + wm * 64 + (lane >> 2);
    const int cBase = blockIdx.x * 128 + wn * 64 + (lane & 3) * 2;
    const long long zC = (long long)blockIdx.z * sC;

#pragma unroll
    for (int mt = 0; mt < 4; ++mt) {
#pragma unroll
        for (int h = 0; h < 2; ++h) {
            const int row = rBase + mt * 16 + h * 8;
#pragma unroll
            for (int nt = 0; nt < 8; ++nt) {
                const int col = cBase + nt * 8;
                float2 fv;
                fv.x = acc[mt][nt][h * 2 + 0];
                fv.y = acc[mt][nt][h * 2 + 1];
                *(float2*)(Cf + zC + (long long)row * ldC + col) = fv;
            }
        }
    }
}

// ---------------------------------------------------------------------------
// Elementwise fp32 -> (hi, lo) bf16 split
// ---------------------------------------------------------------------------
__global__ __launch_bounds__(256)
void convert_split(const float4* __restrict__ in, __nv_bfloat16* __restrict__ oh,
                   __nv_bfloat16* __restrict__ ol, int n4)
{
    __nv_bfloat162* oh2 = reinterpret_cast<__nv_bfloat162*>(oh);
    __nv_bfloat162* ol2 = reinterpret_cast<__nv_bfloat162*>(ol);
    for (int i = blockIdx.x * 256 + threadIdx.x; i < n4; i += gridDim.x * 256) {
        float4 v = in[i];
        __nv_bfloat16 h0, l0, h1, l1, h2, l2, h3, l3;
        split2(v.x, h0, l0); split2(v.y, h1, l1);
        split2(v.z, h2, l2); split2(v.w, h3, l3);
        __nv_bfloat162 a; a.x = h0; a.y = h1;
        __nv_bfloat162 b; b.x = h2; b.y = h3;
        oh2[i * 2] = a; oh2[i * 2 + 1] = b;
        a.x = l0; a.y = l1; b.x = l2; b.y = l3;
        ol2[i * 2] = a; ol2[i * 2 + 1] = b;
    }
}

// ---------------------------------------------------------------------------
// Fused enc prep: read enc once per batch; write row-major bf16 hi/lo AND
// transposed [D][TK] fp16 hi/lo (for the fp16 context GEMM).
// blockDim (32,8), grid (D/32, TK/32, B)
// ---------------------------------------------------------------------------
__global__ __launch_bounds__(256)
void prep_enc(const float* __restrict__ in,
              __nv_bfloat16* __restrict__ rh, __nv_bfloat16* __restrict__ rl,
              __half* __restrict__ th, __half* __restrict__ tl)
{
    __shared__ float t[32][33];
    const long long zi = (long long)blockIdx.z * TK * D;
    const long long zo = (long long)blockIdx.z * D * TK;
    const int c0 = blockIdx.x * 32, r0 = blockIdx.y * 32;
    const int tx = threadIdx.x, ty0 = threadIdx.y;
#pragma unroll
    for (int i = 0; i < 4; ++i) {
        int ty = ty0 + i * 8;
        float v = in[zi + (long long)(r0 + ty) * D + c0 + tx];
        t[ty][tx] = v;
        __nv_bfloat16 h, l; split2(v, h, l);
        long long o = zi + (long long)(r0 + ty) * D + c0 + tx;
        rh[o] = h; rl[o] = l;
    }
    __syncthreads();
#pragma unroll
    for (int i = 0; i < 4; ++i) {
        int ty = ty0 + i * 8;
        float v = t[tx][ty];                 // = in[r0+tx][c0+ty]
        __half h, l; split2h(v, h, l);
        long long o = zo + (long long)(c0 + ty) * TK + r0 + tx;
        th[o] = h; tl[o] = l;
    }
}

// ---------------------------------------------------------------------------
// Transpose + split (for W): in [R][C] fp32 -> out [C][R] bf16 hi/lo
// ---------------------------------------------------------------------------
__global__ __launch_bounds__(256)
void transpose_split(const float* __restrict__ in, __nv_bfloat16* __restrict__ oh,
                     __nv_bfloat16* __restrict__ ol, int R, int C)
{
    __shared__ float t[32][33];
    const int c0 = blockIdx.x * 32, r0 = blockIdx.y * 32;
    const int tx = threadIdx.x, ty0 = threadIdx.y;
#pragma unroll
    for (int i = 0; i < 4; ++i) {
        int ty = ty0 + i * 8;
        t[ty][tx] = in[(long long)(r0 + ty) * C + c0 + tx];
    }
    __syncthreads();
#pragma unroll
    for (int i = 0; i < 4; ++i) {
        int ty = ty0 + i * 8;
        float v = t[tx][ty];
        __nv_bfloat16 h, l; split2(v, h, l);
        long long o = (long long)(c0 + ty) * R + r0 + tx;
        oh[o] = h; ol[o] = l;
    }
}

// ---------------------------------------------------------------------------
// In-place row softmax over 2048 cols + single fp16 output for context GEMM
// ---------------------------------------------------------------------------
__global__ __launch_bounds__(256)
void softmax2048(float* __restrict__ data, __half* __restrict__ alh)
{
    float* row = data + (long long)blockIdx.x * 2048;
    __half2* hrow = reinterpret_cast<__half2*>(alh + (long long)blockIdx.x * 2048);
    const int tid = threadIdx.x;

    float4 v0 = reinterpret_cast<float4*>(row)[tid];
    float4 v1 = reinterpret_cast<float4*>(row)[tid + 256];

    __shared__ float smr[8];
    __shared__ float bcast;

    float m = fmaxf(fmaxf(fmaxf(v0.x, v0.y), fmaxf(v0.z, v0.w)),
                    fmaxf(fmaxf(v1.x, v1.y), fmaxf(v1.z, v1.w)));
#pragma unroll
    for (int o = 16; o > 0; o >>= 1) m = fmaxf(m, __shfl_xor_sync(0xffffffffu, m, o));
    if ((tid & 31) == 0) smr[tid >> 5] = m;
    __syncthreads();
    if (tid == 0) {
        float t = smr[0];
#pragma unroll
        for (int i = 1; i < 8; ++i) t = fmaxf(t, smr[i]);
        bcast = t;
    }
    __syncthreads();
    m = bcast;
    __syncthreads();

    v0.x = __expf(v0.x - m); v0.y = __expf(v0.y - m);
    v0.z = __expf(v0.z - m); v0.w = __expf(v0.w - m);
    v1.x = __expf(v1.x - m); v1.y = __expf(v1.y - m);
    v1.z = __expf(v1.z - m); v1.w = __expf(v1.w - m);
    float s = (v0.x + v0.y) + (v0.z + v0.w) + (v1.x + v1.y) + (v1.z + v1.w);
#pragma unroll
    for (int o = 16; o > 0; o >>= 1) s += __shfl_xor_sync(0xffffffffu, s, o);
    if ((tid & 31) == 0) smr[tid >> 5] = s;
    __syncthreads();
    if (tid == 0) {
        float t = 0.0f;
#pragma unroll
        for (int i = 0; i < 8; ++i) t += smr[i];
        bcast = 1.0f / t;
    }
    __syncthreads();
    const float r = bcast;

    v0.x *= r; v0.y *= r; v0.z *= r; v0.w *= r;
    v1.x *= r; v1.y *= r; v1.z *= r; v1.w *= r;
    reinterpret_cast<float4*>(row)[tid]       = v0;
    reinterpret_cast<float4*>(row)[tid + 256] = v1;

    hrow[tid * 2]             = __floats2half2_rn(v0.x, v0.y);
    hrow[tid * 2 + 1]         = __floats2half2_rn(v0.z, v0.w);
    hrow[(256 + tid) * 2]     = __floats2half2_rn(v1.x, v1.y);
    hrow[(256 + tid) * 2 + 1] = __floats2half2_rn(v1.z, v1.w);
}

// ---------------------------------------------------------------------------
extern "C" void kernel_launch(void* const* d_in, const int* in_sizes, int n_in,
                              void* d_out, int out_size)
{
    const float* dec = (const float*)d_in[0];   // [B, TQ, D]
    const float* enc = (const float*)d_in[1];   // [B, TK, D]
    const float* Wk  = (const float*)d_in[2];   // [D, D]
    const float* bia = (const float*)d_in[3];   // [D]
    if (n_in >= 4 && in_sizes[2] == D && in_sizes[3] == D * D) {
        const float* t = Wk; Wk = bia; bia = t;
    }

    float* out     = (float*)d_out;
    float* context = out;                          // B*TQ*D
    float* align   = out + (size_t)Bsz * TQ * D;   // B*TQ*TK (score scratch too)

    __nv_bfloat16 *dec_h, *dec_l, *enc_h, *enc_l;
    __half *encT_h, *encT_l, *al_f16;
    __nv_bfloat16 *Wt_h, *Wt_l, *key_h, *key_l;
    cudaGetSymbolAddress((void**)&dec_h,  g_dec_h);
    cudaGetSymbolAddress((void**)&dec_l,  g_dec_l);
    cudaGetSymbolAddress((void**)&enc_h,  g_enc_h);
    cudaGetSymbolAddress((void**)&enc_l,  g_enc_l);
    cudaGetSymbolAddress((void**)&encT_h, g_encT_h);
    cudaGetSymbolAddress((void**)&encT_l, g_encT_l);
    cudaGetSymbolAddress((void**)&Wt_h,   g_Wt_h);
    cudaGetSymbolAddress((void**)&Wt_l,   g_Wt_l);
    cudaGetSymbolAddress((void**)&key_h,  g_key_h);
    cudaGetSymbolAddress((void**)&key_l,  g_key_l);
    cudaGetSymbolAddress((void**)&al_f16, g_al_f16);

    cudaFuncSetAttribute(gemm_bf16x3,  cudaFuncAttributeMaxDynamicSharedMemorySize, SMEM_DYN);
    cudaFuncSetAttribute(gemm_ctx_fp16, cudaFuncAttributeMaxDynamicSharedMemorySize, CTX_SMEM);

    // 1) prep
    const int n4 = Bsz * TQ * D / 4;
    convert_split<<<4096, 256>>>((const float4*)dec, dec_h, dec_l, n4);
    prep_enc<<<dim3(D / 32, TK / 32, Bsz), dim3(32, 8)>>>(
        enc, enc_h, enc_l, encT_h, encT_l);
    transpose_split<<<dim3(D / 32, D / 32, 1), dim3(32, 8)>>>(
        Wk, Wt_h, Wt_l, D, D);

    // 2) keys = enc @ W + bias -> split bf16   (M=32768, N=1024, K=1024)
    gemm_bf16x3<<<dim3(D / 128, (Bsz * TK) / 128, 1), 128, SMEM_DYN>>>(
        enc_h, enc_l, Wt_h, Wt_l,
        nullptr, key_h, key_l, bia,
        D, D, 0LL, 0LL, 0LL);

    // 3) score[b] = dec[b] @ keys[b]^T -> fp32 into align region
    gemm_bf16x3<<<dim3(TK / 128, TQ / 128, Bsz), 128, SMEM_DYN>>>(
        dec_h, dec_l, key_h, key_l,
        align, nullptr, nullptr, nullptr,
        D, TK, (long long)TQ * D, (long long)TK * D, (long long)TQ * TK);

    // 4) softmax (in place) + fp16 alignment for context GEMM
    softmax2048<<<Bsz * TQ, 256>>>(align, al_f16);

    // 5) context[b] = align[b] @ enc[b]   (fp16 2-term, B = encT fp16 hi/lo)
    gemm_ctx_fp16<<<dim3(D / 128, TQ / 128, Bsz), 128, CTX_SMEM>>>(
        al_f16, encT_h, encT_l,
        context, TK, D,
        (long long)TQ * TK, (long long)D * TK, (long long)TQ * D);
}

// round 13
// speedup vs baseline: 4.5302x; 1.1768x over previous
#include <cuda_runtime.h>
#include <cuda_bf16.h>
#include <cuda_fp16.h>
#include <cstdint>

// LuongAttention B=16, TQ=2048, TK=2048, D=1024
// out = [context (B*TQ*D fp32) | alignment (B*TQ*TK fp32)]
static constexpr int Bsz = 16;
static constexpr int TQ  = 2048;
static constexpr int TK  = 2048;
static constexpr int D   = 1024;

// ---------------- device scratch (allocation-free, 16B aligned) ----------------
__device__ __align__(16) __nv_bfloat16 g_dec_h[(size_t)Bsz * TQ * D];
__device__ __align__(16) __nv_bfloat16 g_dec_l[(size_t)Bsz * TQ * D];
__device__ __align__(16) __nv_bfloat16 g_enc_h[(size_t)Bsz * TK * D];
__device__ __align__(16) __nv_bfloat16 g_enc_l[(size_t)Bsz * TK * D];
__device__ __align__(16) __half        g_encT_h[(size_t)Bsz * D * TK];   // fp16 (single)
__device__ __align__(16) __nv_bfloat16 g_Wt_h[(size_t)D * D];
__device__ __align__(16) __nv_bfloat16 g_Wt_l[(size_t)D * D];
__device__ __align__(16) __nv_bfloat16 g_key_h[(size_t)Bsz * TK * D];
__device__ __align__(16) __nv_bfloat16 g_key_l[(size_t)Bsz * TK * D];
__device__ __align__(16) __half        g_al_f16[(size_t)Bsz * TQ * TK];  // fp16 alignment

// ---------------- helpers ----------------
__device__ __forceinline__ uint32_t smem_u32(const void* p) {
    uint32_t a;
    asm("{ .reg .u64 t; cvta.to.shared.u64 t, %1; cvt.u32.u64 %0, t; }"
        : "=r"(a) : "l"(p));
    return a;
}
__device__ __forceinline__ void cp_async16(uint32_t dst, const void* src) {
    asm volatile("{ .reg .u64 g; cvta.to.global.u64 g, %1;"
                 "  cp.async.cg.shared.global [%0], [g], 16; }"
                 :: "r"(dst), "l"(src) : "memory");
}
#define CP_COMMIT() asm volatile("cp.async.commit_group;" ::: "memory")
#define CP_WAIT1()  asm volatile("cp.async.wait_group 1;" ::: "memory")
#define CP_WAIT0()  asm volatile("cp.async.wait_group 0;" ::: "memory")

__device__ __forceinline__ void ldm_x4(uint32_t* r, uint32_t addr) {
    asm volatile("ldmatrix.sync.aligned.m8n8.x4.shared.b16 {%0,%1,%2,%3}, [%4];"
                 : "=r"(r[0]), "=r"(r[1]), "=r"(r[2]), "=r"(r[3]) : "r"(addr));
}
__device__ __forceinline__ void mma_bf16(float* c, const uint32_t* a, const uint32_t* b) {
    asm volatile("mma.sync.aligned.m16n8k16.row.col.f32.bf16.bf16.f32 "
                 "{%0,%1,%2,%3}, {%4,%5,%6,%7}, {%8,%9}, {%0,%1,%2,%3};"
                 : "+f"(c[0]), "+f"(c[1]), "+f"(c[2]), "+f"(c[3])
                 : "r"(a[0]), "r"(a[1]), "r"(a[2]), "r"(a[3]), "r"(b[0]), "r"(b[1]));
}
__device__ __forceinline__ void mma_fp16(float* c, const uint32_t* a, const uint32_t* b) {
    asm volatile("mma.sync.aligned.m16n8k16.row.col.f32.f16.f16.f32 "
                 "{%0,%1,%2,%3}, {%4,%5,%6,%7}, {%8,%9}, {%0,%1,%2,%3};"
                 : "+f"(c[0]), "+f"(c[1]), "+f"(c[2]), "+f"(c[3])
                 : "r"(a[0]), "r"(a[1]), "r"(a[2]), "r"(a[3]), "r"(b[0]), "r"(b[1]));
}
__device__ __forceinline__ void split2(float x, __nv_bfloat16& h, __nv_bfloat16& l) {
    h = __float2bfloat16_rn(x);
    l = __float2bfloat16_rn(x - __bfloat162float(h));
}

// smem geometry: 128 rows x 64B (32 elems), XOR swizzle -> no padding
static constexpr int TILE_B  = 128 * 64;        // 8192 B per tile array
static constexpr int STAGE_B = 4 * TILE_B;      // Ah,Al,Bh,Bl = 32768 B
static constexpr int NSTAGE  = 3;
static constexpr int SMEM_DYN = NSTAGE * STAGE_B;  // 98304 B

static constexpr int CTX_STAGE_B = 2 * TILE_B;     // A,B = 16384 B
static constexpr int CTX_SMEM    = NSTAGE * CTX_STAGE_B;  // 49152 B

__device__ __forceinline__ uint32_t sw_addr(int row, int chunk) {
    return (uint32_t)(row * 64 + ((chunk ^ ((row >> 1) & 3)) << 4));
}

// ---------------------------------------------------------------------------
// bf16x3 GEMM (emulated fp32) on mma.sync:  C[M,N] = A[M,K] * B[N,K]^T
// Tile 128x128, BK=32, 128 thr (4 warps, 2Mx2N, warp tile 64x64)
// 3-stage cp.async pipeline, one __syncthreads per K-iteration.
// ---------------------------------------------------------------------------
__global__ __launch_bounds__(128, 2)
void gemm_bf16x3(const __nv_bfloat16* __restrict__ Ah, const __nv_bfloat16* __restrict__ Al,
                 const __nv_bfloat16* __restrict__ Bh, const __nv_bfloat16* __restrict__ Bl,
                 float* __restrict__ Cf,
                 __nv_bfloat16* __restrict__ Chi, __nv_bfloat16* __restrict__ Clo,
                 const float* __restrict__ bias,
                 int K, int ldC,
                 long long sA, long long sB, long long sC)
{
    extern __shared__ __align__(128) char sm[];
    const uint32_t s0 = smem_u32(sm);

    const int tid  = threadIdx.x;
    const int wid  = tid >> 5;
    const int lane = tid & 31;
    const int wm   = wid & 1;
    const int wn   = wid >> 1;

    const long long zA = (long long)blockIdx.z * sA;
    const long long zB = (long long)blockIdx.z * sB;
    const __nv_bfloat16* pAh = Ah + zA + (long long)(blockIdx.y * 128) * K;
    const __nv_bfloat16* pAl = Al + zA + (long long)(blockIdx.y * 128) * K;
    const __nv_bfloat16* pBh = Bh + zB + (long long)(blockIdx.x * 128) * K;
    const __nv_bfloat16* pBl = Bl + zB + (long long)(blockIdx.x * 128) * K;

    const int lr0 = tid >> 2;
    const int lc  = tid & 3;
    auto tileLoad = [&](int stage, int k0) {
        const uint32_t db = s0 + stage * STAGE_B;
#pragma unroll
        for (int i = 0; i < 4; ++i) {
            const int r = lr0 + i * 32;
            const uint32_t so = sw_addr(r, lc);
            const long long go = (long long)r * K + k0 + lc * 8;
            cp_async16(db + 0 * TILE_B + so, pAh + go);
            cp_async16(db + 1 * TILE_B + so, pAl + go);
            cp_async16(db + 2 * TILE_B + so, pBh + go);
            cp_async16(db + 3 * TILE_B + so, pBl + go);
        }
        CP_COMMIT();
    };

    const int rowA0 = wm * 64 + (lane & 15);
    const int hiA   = lane >> 4;
    const int rowB0 = wn * 64 + (lane & 7) + ((lane & 16) >> 1);
    const int hiB   = (lane & 8) >> 3;

    float acc[4][8][4];
#pragma unroll
    for (int a = 0; a < 4; ++a)
#pragma unroll
        for (int b = 0; b < 8; ++b)
#pragma unroll
            for (int c = 0; c < 4; ++c) acc[a][b][c] = 0.0f;

    const int nk = K >> 5;
    tileLoad(0, 0);
    tileLoad(1, 32);

    int stage = 0;
    for (int it = 0; it < nk; ++it) {
        if (it + 2 < nk) { CP_WAIT1(); } else { CP_WAIT0(); }
        __syncthreads();
        if (it + 2 < nk) {
            int ns = stage + 2; if (ns >= NSTAGE) ns -= NSTAGE;
            tileLoad(ns, (it + 2) << 5);
        }

        const uint32_t sb = s0 + stage * STAGE_B;
#pragma unroll
        for (int ks = 0; ks < 2; ++ks) {
            uint32_t fAh[4][4], fAl[4][4], fBh[4][4], fBl[4][4];
#pragma unroll
            for (int mt = 0; mt < 4; ++mt) {
                const int r = rowA0 + mt * 16;
                const uint32_t ao = sw_addr(r, hiA + ks * 2);
                ldm_x4(fAh[mt], sb + 0 * TILE_B + ao);
                ldm_x4(fAl[mt], sb + 1 * TILE_B + ao);
            }
#pragma unroll
            for (int pp = 0; pp < 4; ++pp) {
                const int rb = rowB0 + pp * 16;
                const uint32_t bo = sw_addr(rb, hiB + ks * 2);
                ldm_x4(fBh[pp], sb + 2 * TILE_B + bo);
                ldm_x4(fBl[pp], sb + 3 * TILE_B + bo);
            }
#pragma unroll
            for (int pp = 0; pp < 4; ++pp) {
#pragma unroll
                for (int q = 0; q < 2; ++q) {
                    const int nt = pp * 2 + q;
#pragma unroll
                    for (int mt = 0; mt < 4; ++mt)
                        mma_bf16(acc[mt][nt], fAh[mt], fBh[pp] + q * 2);
#pragma unroll
                    for (int mt = 0; mt < 4; ++mt)
                        mma_bf16(acc[mt][nt], fAh[mt], fBl[pp] + q * 2);
#pragma unroll
                    for (int mt = 0; mt < 4; ++mt)
                        mma_bf16(acc[mt][nt], fAl[mt], fBh[pp] + q * 2);
                }
            }
        }
        if (++stage >= NSTAGE) stage = 0;
    }

    // ---------------- epilogue ----------------
    const int rBase = blockIdx.y * 128 + wm * 64 + (lane >> 2);
    const int cBase = blockIdx.x * 128 + wn * 64 + (lane & 3) * 2;
    const long long zC = (long long)blockIdx.z * sC;

#pragma unroll
    for (int mt = 0; mt < 4; ++mt) {
#pragma unroll
        for (int h = 0; h < 2; ++h) {
            const int row = rBase + mt * 16 + h * 8;
#pragma unroll
            for (int nt = 0; nt < 8; ++nt) {
                const int col = cBase + nt * 8;
                float v0 = acc[mt][nt][h * 2 + 0];
                float v1 = acc[mt][nt][h * 2 + 1];
                if (bias) { v0 += bias[col]; v1 += bias[col + 1]; }
                const long long o = zC + (long long)row * ldC + col;
                if (Cf) {
                    float2 fv; fv.x = v0; fv.y = v1;
                    *(float2*)(Cf + o) = fv;
                }
                if (Chi) {
                    __nv_bfloat16 h0, l0, h1, l1;
                    split2(v0, h0, l0); split2(v1, h1, l1);
                    __nv_bfloat162 hv; hv.x = h0; hv.y = h1;
                    __nv_bfloat162 lv; lv.x = l0; lv.y = l1;
                    *(__nv_bfloat162*)(Chi + o) = hv;
                    *(__nv_bfloat162*)(Clo + o) = lv;
                }
            }
        }
    }
}

// ---------------------------------------------------------------------------
// fp16 1-term GEMM for context: C[M,N] = A[M,K] * B[N,K]^T
// A fp16 alignment (in [0,1]), B fp16 enc. Error budget: ~2^-12 rms each,
// linear sensitivity -> context rel err ~2-4e-4 total.
// ---------------------------------------------------------------------------
__global__ __launch_bounds__(128, 2)
void gemm_ctx_fp16(const __half* __restrict__ A,
                   const __half* __restrict__ B,
                   float* __restrict__ Cf,
                   int K, int ldC,
                   long long sA, long long sB, long long sC)
{
    extern __shared__ __align__(128) char sm[];
    const uint32_t s0 = smem_u32(sm);

    const int tid  = threadIdx.x;
    const int wid  = tid >> 5;
    const int lane = tid & 31;
    const int wm   = wid & 1;
    const int wn   = wid >> 1;

    const long long zA = (long long)blockIdx.z * sA;
    const long long zB = (long long)blockIdx.z * sB;
    const __half* pA = A + zA + (long long)(blockIdx.y * 128) * K;
    const __half* pB = B + zB + (long long)(blockIdx.x * 128) * K;

    const int lr0 = tid >> 2;
    const int lc  = tid & 3;
    auto tileLoad = [&](int stage, int k0) {
        const uint32_t db = s0 + stage * CTX_STAGE_B;
#pragma unroll
        for (int i = 0; i < 4; ++i) {
            const int r = lr0 + i * 32;
            const uint32_t so = sw_addr(r, lc);
            const long long go = (long long)r * K + k0 + lc * 8;
            cp_async16(db + 0 * TILE_B + so, pA + go);
            cp_async16(db + 1 * TILE_B + so, pB + go);
        }
        CP_COMMIT();
    };

    const int rowA0 = wm * 64 + (lane & 15);
    const int hiA   = lane >> 4;
    const int rowB0 = wn * 64 + (lane & 7) + ((lane & 16) >> 1);
    const int hiB   = (lane & 8) >> 3;

    float acc[4][8][4];
#pragma unroll
    for (int a = 0; a < 4; ++a)
#pragma unroll
        for (int b = 0; b < 8; ++b)
#pragma unroll
            for (int c = 0; c < 4; ++c) acc[a][b][c] = 0.0f;

    const int nk = K >> 5;
    tileLoad(0, 0);
    tileLoad(1, 32);

    int stage = 0;
    for (int it = 0; it < nk; ++it) {
        if (it + 2 < nk) { CP_WAIT1(); } else { CP_WAIT0(); }
        __syncthreads();
        if (it + 2 < nk) {
            int ns = stage + 2; if (ns >= NSTAGE) ns -= NSTAGE;
            tileLoad(ns, (it + 2) << 5);
        }

        const uint32_t sb = s0 + stage * CTX_STAGE_B;
#pragma unroll
        for (int ks = 0; ks < 2; ++ks) {
            uint32_t fA[4][4], fB[4][4];
#pragma unroll
            for (int mt = 0; mt < 4; ++mt) {
                const int r = rowA0 + mt * 16;
                const uint32_t ao = sw_addr(r, hiA + ks * 2);
                ldm_x4(fA[mt], sb + 0 * TILE_B + ao);
            }
#pragma unroll
            for (int pp = 0; pp < 4; ++pp) {
                const int rb = rowB0 + pp * 16;
                const uint32_t bo = sw_addr(rb, hiB + ks * 2);
                ldm_x4(fB[pp], sb + 1 * TILE_B + bo);
            }
#pragma unroll
            for (int pp = 0; pp < 4; ++pp) {
#pragma unroll
                for (int q = 0; q < 2; ++q) {
                    const int nt = pp * 2 + q;
#pragma unroll
                    for (int mt = 0; mt < 4; ++mt)
                        mma_fp16(acc[mt][nt], fA[mt], fB[pp] + q * 2);
                }
            }
        }
        if (++stage >= NSTAGE) stage = 0;
    }

    // ---------------- epilogue ----------------
    const int rBase = blockIdx.y * 128 + wm * 64 + (lane >> 2);
    const int cBase = blockIdx.x * 128 + wn * 64 + (lane & 3) * 2;
    const long long zC = (long long)blockIdx.z * sC;

#pragma unroll
    for (int mt = 0; mt < 4; ++mt) {
#pragma unroll
        for (int h = 0; h < 2; ++h) {
            const int row = rBase + mt * 16 + h * 8;
#pragma unroll
            for (int nt = 0; nt < 8; ++nt) {
                const int col = cBase + nt * 8;
                float2 fv;
                fv.x = acc[mt][nt][h * 2 + 0];
                fv.y = acc[mt][nt][h * 2 + 1];
                *(float2*)(Cf + zC + (long long)row * ldC + col) = fv;
            }
        }
    }
}

// ---------------------------------------------------------------------------
// Elementwise fp32 -> (hi, lo) bf16 split
// ---------------------------------------------------------------------------
__global__ __launch_bounds__(256)
void convert_split(const float4* __restrict__ in, __nv_bfloat16* __restrict__ oh,
                   __nv_bfloat16* __restrict__ ol, int n4)
{
    __nv_bfloat162* oh2 = reinterpret_cast<__nv_bfloat162*>(oh);
    __nv_bfloat162* ol2 = reinterpret_cast<__nv_bfloat162*>(ol);
    for (int i = blockIdx.x * 256 + threadIdx.x; i < n4; i += gridDim.x * 256) {
        float4 v = in[i];
        __nv_bfloat16 h0, l0, h1, l1, h2, l2, h3, l3;
        split2(v.x, h0, l0); split2(v.y, h1, l1);
        split2(v.z, h2, l2); split2(v.w, h3, l3);
        __nv_bfloat162 a; a.x = h0; a.y = h1;
        __nv_bfloat162 b; b.x = h2; b.y = h3;
        oh2[i * 2] = a; oh2[i * 2 + 1] = b;
        a.x = l0; a.y = l1; b.x = l2; b.y = l3;
        ol2[i * 2] = a; ol2[i * 2 + 1] = b;
    }
}

// ---------------------------------------------------------------------------
// Fused enc prep: read enc once per batch; write row-major bf16 hi/lo AND
// transposed [D][TK] single fp16 (for the 1-term context GEMM).
// blockDim (32,8), grid (D/32, TK/32, B)
// ---------------------------------------------------------------------------
__global__ __launch_bounds__(256)
void prep_enc(const float* __restrict__ in,
              __nv_bfloat16* __restrict__ rh, __nv_bfloat16* __restrict__ rl,
              __half* __restrict__ th)
{
    __shared__ float t[32][33];
    const long long zi = (long long)blockIdx.z * TK * D;
    const long long zo = (long long)blockIdx.z * D * TK;
    const int c0 = blockIdx.x * 32, r0 = blockIdx.y * 32;
    const int tx = threadIdx.x, ty0 = threadIdx.y;
#pragma unroll
    for (int i = 0; i < 4; ++i) {
        int ty = ty0 + i * 8;
        float v = in[zi + (long long)(r0 + ty) * D + c0 + tx];
        t[ty][tx] = v;
        __nv_bfloat16 h, l; split2(v, h, l);
        long long o = zi + (long long)(r0 + ty) * D + c0 + tx;
        rh[o] = h; rl[o] = l;
    }
    __syncthreads();
#pragma unroll
    for (int i = 0; i < 4; ++i) {
        int ty = ty0 + i * 8;
        float v = t[tx][ty];                 // = in[r0+tx][c0+ty]
        long long o = zo + (long long)(c0 + ty) * TK + r0 + tx;
        th[o] = __float2half_rn(v);
    }
}

// ---------------------------------------------------------------------------
// Transpose + split (for W): in [R][C] fp32 -> out [C][R] bf16 hi/lo
// ---------------------------------------------------------------------------
__global__ __launch_bounds__(256)
void transpose_split(const float* __restrict__ in, __nv_bfloat16* __restrict__ oh,
                     __nv_bfloat16* __restrict__ ol, int R, int C)
{
    __shared__ float t[32][33];
    const int c0 = blockIdx.x * 32, r0 = blockIdx.y * 32;
    const int tx = threadIdx.x, ty0 = threadIdx.y;
#pragma unroll
    for (int i = 0; i < 4; ++i) {
        int ty = ty0 + i * 8;
        t[ty][tx] = in[(long long)(r0 + ty) * C + c0 + tx];
    }
    __syncthreads();
#pragma unroll
    for (int i = 0; i < 4; ++i) {
        int ty = ty0 + i * 8;
        float v = t[tx][ty];
        __nv_bfloat16 h, l; split2(v, h, l);
        long long o = (long long)(c0 + ty) * R + r0 + tx;
        oh[o] = h; ol[o] = l;
    }
}

// ---------------------------------------------------------------------------
// In-place row softmax over 2048 cols + single fp16 output for context GEMM
// ---------------------------------------------------------------------------
__global__ __launch_bounds__(256)
void softmax2048(float* __restrict__ data, __half* __restrict__ alh)
{
    float* row = data + (long long)blockIdx.x * 2048;
    __half2* hrow = reinterpret_cast<__half2*>(alh + (long long)blockIdx.x * 2048);
    const int tid = threadIdx.x;

    float4 v0 = reinterpret_cast<float4*>(row)[tid];
    float4 v1 = reinterpret_cast<float4*>(row)[tid + 256];

    __shared__ float smr[8];
    __shared__ float bcast;

    float m = fmaxf(fmaxf(fmaxf(v0.x, v0.y), fmaxf(v0.z, v0.w)),
                    fmaxf(fmaxf(v1.x, v1.y), fmaxf(v1.z, v1.w)));
#pragma unroll
    for (int o = 16; o > 0; o >>= 1) m = fmaxf(m, __shfl_xor_sync(0xffffffffu, m, o));
    if ((tid & 31) == 0) smr[tid >> 5] = m;
    __syncthreads();
    if (tid == 0) {
        float t = smr[0];
#pragma unroll
        for (int i = 1; i < 8; ++i) t = fmaxf(t, smr[i]);
        bcast = t;
    }
    __syncthreads();
    m = bcast;
    __syncthreads();

    v0.x = __expf(v0.x - m); v0.y = __expf(v0.y - m);
    v0.z = __expf(v0.z - m); v0.w = __expf(v0.w - m);
    v1.x = __expf(v1.x - m); v1.y = __expf(v1.y - m);
    v1.z = __expf(v1.z - m); v1.w = __expf(v1.w - m);
    float s = (v0.x + v0.y) + (v0.z + v0.w) + (v1.x + v1.y) + (v1.z + v1.w);
#pragma unroll
    for (int o = 16; o > 0; o >>= 1) s += __shfl_xor_sync(0xffffffffu, s, o);
    if ((tid & 31) == 0) smr[tid >> 5] = s;
    __syncthreads();
    if (tid == 0) {
        float t = 0.0f;
#pragma unroll
        for (int i = 0; i < 8; ++i) t += smr[i];
        bcast = 1.0f / t;
    }
    __syncthreads();
    const float r = bcast;

    v0.x *= r; v0.y *= r; v0.z *= r; v0.w *= r;
    v1.x *= r; v1.y *= r; v1.z *= r; v1.w *= r;
    reinterpret_cast<float4*>(row)[tid]       = v0;
    reinterpret_cast<float4*>(row)[tid + 256] = v1;

    hrow[tid * 2]             = __floats2half2_rn(v0.x, v0.y);
    hrow[tid * 2 + 1]         = __floats2half2_rn(v0.z, v0.w);
    hrow[(256 + tid) * 2]     = __floats2half2_rn(v1.x, v1.y);
    hrow[(256 + tid) * 2 + 1] = __floats2half2_rn(v1.z, v1.w);
}

// ---------------------------------------------------------------------------
extern "C" void kernel_launch(void* const* d_in, const int* in_sizes, int n_in,
                              void* d_out, int out_size)
{
    const float* dec = (const float*)d_in[0];   // [B, TQ, D]
    const float* enc = (const float*)d_in[1];   // [B, TK, D]
    const float* Wk  = (const float*)d_in[2];   // [D, D]
    const float* bia = (const float*)d_in[3];   // [D]
    if (n_in >= 4 && in_sizes[2] == D && in_sizes[3] == D * D) {
        const float* t = Wk; Wk = bia; bia = t;
    }

    float* out     = (float*)d_out;
    float* context = out;                          // B*TQ*D
    float* align   = out + (size_t)Bsz * TQ * D;   // B*TQ*TK (score scratch too)

    __nv_bfloat16 *dec_h, *dec_l, *enc_h, *enc_l;
    __half *encT_h, *al_f16;
    __nv_bfloat16 *Wt_h, *Wt_l, *key_h, *key_l;
    cudaGetSymbolAddress((void**)&dec_h,  g_dec_h);
    cudaGetSymbolAddress((void**)&dec_l,  g_dec_l);
    cudaGetSymbolAddress((void**)&enc_h,  g_enc_h);
    cudaGetSymbolAddress((void**)&enc_l,  g_enc_l);
    cudaGetSymbolAddress((void**)&encT_h, g_encT_h);
    cudaGetSymbolAddress((void**)&Wt_h,   g_Wt_h);
    cudaGetSymbolAddress((void**)&Wt_l,   g_Wt_l);
    cudaGetSymbolAddress((void**)&key_h,  g_key_h);
    cudaGetSymbolAddress((void**)&key_l,  g_key_l);
    cudaGetSymbolAddress((void**)&al_f16, g_al_f16);

    cudaFuncSetAttribute(gemm_bf16x3,   cudaFuncAttributeMaxDynamicSharedMemorySize, SMEM_DYN);
    cudaFuncSetAttribute(gemm_ctx_fp16, cudaFuncAttributeMaxDynamicSharedMemorySize, CTX_SMEM);

    // 1) prep
    const int n4 = Bsz * TQ * D / 4;
    convert_split<<<4096, 256>>>((const float4*)dec, dec_h, dec_l, n4);
    prep_enc<<<dim3(D / 32, TK / 32, Bsz), dim3(32, 8)>>>(
        enc, enc_h, enc_l, encT_h);
    transpose_split<<<dim3(D / 32, D / 32, 1), dim3(32, 8)>>>(
        Wk, Wt_h, Wt_l, D, D);

    // 2) keys = enc @ W + bias -> split bf16   (M=32768, N=1024, K=1024)
    gemm_bf16x3<<<dim3(D / 128, (Bsz * TK) / 128, 1), 128, SMEM_DYN>>>(
        enc_h, enc_l, Wt_h, Wt_l,
        nullptr, key_h, key_l, bia,
        D, D, 0LL, 0LL, 0LL);

    // 3) score[b] = dec[b] @ keys[b]^T -> fp32 into align region
    gemm_bf16x3<<<dim3(TK / 128, TQ / 128, Bsz), 128, SMEM_DYN>>>(
        dec_h, dec_l, key_h, key_l,
        align, nullptr, nullptr, nullptr,
        D, TK, (long long)TQ * D, (long long)TK * D, (long long)TQ * TK);

    // 4) softmax (in place) + fp16 alignment for context GEMM
    softmax2048<<<Bsz * TQ, 256>>>(align, al_f16);

    // 5) context[b] = align[b] @ enc[b]   (fp16 1-term, B = encT fp16)
    gemm_ctx_fp16<<<dim3(D / 128, TQ / 128, Bsz), 128, CTX_SMEM>>>(
        al_f16, encT_h,
        context, TK, D,
        (long long)TQ * TK, (long long)D * TK, (long long)TQ * D);
}